// round 4
// baseline (speedup 1.0000x reference)
#include <cuda_runtime.h>
#include <cuda_bf16.h>
#include <stdint.h>

#define N_NODES 50000
#define N_EDGES 1000000
#define IN_SIZE 256
#define OUT_SIZE 128
#define N_ET 3
#define N_TOT (N_ET * N_NODES)          // 150000
#define TOTAL_E (N_ET * N_EDGES)        // 3000000
#define SCAN_CHUNK 2048
#define SCAN_BLOCKS ((N_TOT + SCAN_CHUNK - 1) / SCAN_CHUNK)   // 74

#define GEMM_BX ((N_NODES + 127) / 128)         // 391
#define GEMM_BLOCKS (GEMM_BX * N_ET)            // 1173
#define FILL_BLOCKS 2930                        // 3M edges / (256*4)
#define FUSED_BLOCKS (GEMM_BLOCKS + FILL_BLOCKS)

// Scratch
__device__ float g_Wh[(size_t)N_ET * N_NODES * OUT_SIZE];     // 76.8 MB
__device__ int   g_cnt[N_TOT];                                 // stays zero between calls
__device__ int   g_off[N_TOT + 1];
__device__ int   g_pos[N_TOT];
__device__ int   g_part[SCAN_BLOCKS];
__device__ int   g_eidx[TOTAL_E];       // src node per edge, dst-sorted

// ---------------------------------------------------------------------------
// CSR build
// ---------------------------------------------------------------------------
__global__ void hist_kernel(const int* __restrict__ edst) {
    int base = (blockIdx.x * blockDim.x + threadIdx.x) * 4;
    if (base >= TOTAL_E) return;
    if (base + 4 <= TOTAL_E) {
        int4 d4 = *(const int4*)&edst[base];
        // all 4 edges share etype block boundaries only at multiples of N_EDGES
        int et0 = base / N_EDGES;
        int et3 = (base + 3) / N_EDGES;
        if (et0 == et3) {
            int o = et0 * N_NODES;
            atomicAdd(&g_cnt[o + d4.x], 1);
            atomicAdd(&g_cnt[o + d4.y], 1);
            atomicAdd(&g_cnt[o + d4.z], 1);
            atomicAdd(&g_cnt[o + d4.w], 1);
        } else {
            atomicAdd(&g_cnt[((base + 0) / N_EDGES) * N_NODES + d4.x], 1);
            atomicAdd(&g_cnt[((base + 1) / N_EDGES) * N_NODES + d4.y], 1);
            atomicAdd(&g_cnt[((base + 2) / N_EDGES) * N_NODES + d4.z], 1);
            atomicAdd(&g_cnt[((base + 3) / N_EDGES) * N_NODES + d4.w], 1);
        }
    } else {
        for (int i = base; i < TOTAL_E; i++)
            atomicAdd(&g_cnt[(i / N_EDGES) * N_NODES + __ldg(&edst[i])], 1);
    }
}

__global__ __launch_bounds__(256) void scan_a_kernel() {
    __shared__ int s[256];
    const int tid = threadIdx.x;
    const int base = blockIdx.x * SCAN_CHUNK + tid * 8;
    int v[8];
    int tsum = 0;
#pragma unroll
    for (int k = 0; k < 8; k++) {
        int i = base + k;
        v[k] = (i < N_TOT) ? g_cnt[i] : 0;
        if (i < N_TOT) g_cnt[i] = 0;        // leave zeroed for next replay
        tsum += v[k];
    }
    s[tid] = tsum;
    __syncthreads();
    for (int off = 1; off < 256; off <<= 1) {
        int t = (tid >= off) ? s[tid - off] : 0;
        __syncthreads();
        s[tid] += t;
        __syncthreads();
    }
    int run = s[tid] - tsum;
#pragma unroll
    for (int k = 0; k < 8; k++) {
        int i = base + k;
        if (i < N_TOT) g_off[i] = run;
        run += v[k];
    }
    if (tid == 255) g_part[blockIdx.x] = s[255];
}

__global__ __launch_bounds__(128) void scan_b_kernel() {
    __shared__ int s[128];
    int tid = threadIdx.x;
    int v = (tid < SCAN_BLOCKS) ? g_part[tid] : 0;
    s[tid] = v;
    __syncthreads();
    for (int off = 1; off < 128; off <<= 1) {
        int t = (tid >= off) ? s[tid - off] : 0;
        __syncthreads();
        s[tid] += t;
        __syncthreads();
    }
    if (tid < SCAN_BLOCKS) g_part[tid] = s[tid] - v;   // exclusive
    if (tid == 127) g_off[N_TOT] = s[127];
}

__global__ void scan_c_kernel() {
    int i = blockIdx.x * blockDim.x + threadIdx.x;
    if (i >= N_TOT) return;
    int o = g_off[i] + g_part[i / SCAN_CHUNK];
    g_off[i] = o;
    g_pos[i] = o;
}

// ---------------------------------------------------------------------------
// TF32 helpers
// ---------------------------------------------------------------------------
__device__ __forceinline__ float tf32_rna(float x) {
    uint32_t u;
    asm("cvt.rna.tf32.f32 %0, %1;" : "=r"(u) : "f"(x));
    return __uint_as_float(u);
}

#define MMA_TF32(D, A, B)                                                     \
    asm volatile(                                                             \
        "mma.sync.aligned.m16n8k8.row.col.f32.tf32.tf32.f32 "                 \
        "{%0,%1,%2,%3}, {%4,%5,%6,%7}, {%8,%9}, {%0,%1,%2,%3};"               \
        : "+f"(D[0]), "+f"(D[1]), "+f"(D[2]), "+f"(D[3])                      \
        : "r"(A[0]), "r"(A[1]), "r"(A[2]), "r"(A[3]), "r"(B[0]), "r"(B[1]))

#define AS_STRIDE 20

// ---------------------------------------------------------------------------
// Fused: GEMM tiles (blocks [0, GEMM_BLOCKS)) + CSR fill (remaining blocks).
// Both only depend on scan_c; they run concurrently in one launch.
// ---------------------------------------------------------------------------
__global__ __launch_bounds__(256, 1) void gemm_fill_kernel(const float* __restrict__ x,
                                                           const float* __restrict__ W,
                                                           const int* __restrict__ esrc,
                                                           const int* __restrict__ edst) {
    __shared__ float As_hi[128 * AS_STRIDE];
    __shared__ float As_lo[128 * AS_STRIDE];
    __shared__ float Ws_hi[128 * AS_STRIDE];
    __shared__ float Ws_lo[128 * AS_STRIDE];

    if (blockIdx.x >= GEMM_BLOCKS) {
        // ---- CSR fill path ----
        int fb = blockIdx.x - GEMM_BLOCKS;
        int base = (fb * 256 + threadIdx.x) * 4;
#pragma unroll
        for (int k = 0; k < 4; k++) {
            int i = base + k;
            if (i < TOTAL_E) {
                int et = i / N_EDGES;
                int d = __ldg(&edst[i]);
                int s = __ldg(&esrc[i]);
                int p = atomicAdd(&g_pos[et * N_NODES + d], 1);
                g_eidx[p] = s;
            }
        }
        return;
    }

    // ---- GEMM path ----
    const int et = blockIdx.x / GEMM_BX;
    const int m0 = (blockIdx.x % GEMM_BX) * 128;
    const int tid = threadIdx.x;
    const int wid = tid >> 5;
    const int lane = tid & 31;
    const int m_off = (wid >> 1) * 32;
    const int n_off = (wid & 1) * 64;
    const int gq = lane >> 2;
    const int tg = lane & 3;

    const float* Wt = W + (size_t)et * IN_SIZE * OUT_SIZE;

    float acc[2][8][4];
#pragma unroll
    for (int i = 0; i < 2; i++)
#pragma unroll
        for (int j = 0; j < 8; j++)
#pragma unroll
            for (int c = 0; c < 4; c++) acc[i][j][c] = 0.0f;

    for (int k0 = 0; k0 < IN_SIZE; k0 += 16) {
#pragma unroll
        for (int i = 0; i < 2; i++) {
            int f4 = tid + i * 256;
            int row = f4 >> 2;
            int kc = (f4 & 3) * 4;
            int gm = m0 + row;
            float4 v = make_float4(0.f, 0.f, 0.f, 0.f);
            if (gm < N_NODES) v = *(const float4*)&x[(size_t)gm * IN_SIZE + k0 + kc];
            float4 h, l;
            h.x = tf32_rna(v.x); l.x = tf32_rna(v.x - h.x);
            h.y = tf32_rna(v.y); l.y = tf32_rna(v.y - h.y);
            h.z = tf32_rna(v.z); l.z = tf32_rna(v.z - h.z);
            h.w = tf32_rna(v.w); l.w = tf32_rna(v.w - h.w);
            *(float4*)&As_hi[row * AS_STRIDE + kc] = h;
            *(float4*)&As_lo[row * AS_STRIDE + kc] = l;
        }
#pragma unroll
        for (int i = 0; i < 2; i++) {
            int f4 = tid + i * 256;
            int kr = f4 >> 5;
            int nc = (f4 & 31) * 4;
            float4 v = *(const float4*)&Wt[(size_t)(k0 + kr) * OUT_SIZE + nc];
            float h, l;
            h = tf32_rna(v.x); l = tf32_rna(v.x - h);
            Ws_hi[(nc + 0) * AS_STRIDE + kr] = h; Ws_lo[(nc + 0) * AS_STRIDE + kr] = l;
            h = tf32_rna(v.y); l = tf32_rna(v.y - h);
            Ws_hi[(nc + 1) * AS_STRIDE + kr] = h; Ws_lo[(nc + 1) * AS_STRIDE + kr] = l;
            h = tf32_rna(v.z); l = tf32_rna(v.z - h);
            Ws_hi[(nc + 2) * AS_STRIDE + kr] = h; Ws_lo[(nc + 2) * AS_STRIDE + kr] = l;
            h = tf32_rna(v.w); l = tf32_rna(v.w - h);
            Ws_hi[(nc + 3) * AS_STRIDE + kr] = h; Ws_lo[(nc + 3) * AS_STRIDE + kr] = l;
        }
        __syncthreads();

#pragma unroll
        for (int ks = 0; ks < 16; ks += 8) {
            uint32_t ahi[2][4], alo[2][4];
#pragma unroll
            for (int mf = 0; mf < 2; mf++) {
                int r = m_off + mf * 16 + gq;
                int c = ks + tg;
                ahi[mf][0] = __float_as_uint(As_hi[r * AS_STRIDE + c]);
                ahi[mf][1] = __float_as_uint(As_hi[(r + 8) * AS_STRIDE + c]);
                ahi[mf][2] = __float_as_uint(As_hi[r * AS_STRIDE + c + 4]);
                ahi[mf][3] = __float_as_uint(As_hi[(r + 8) * AS_STRIDE + c + 4]);
                alo[mf][0] = __float_as_uint(As_lo[r * AS_STRIDE + c]);
                alo[mf][1] = __float_as_uint(As_lo[(r + 8) * AS_STRIDE + c]);
                alo[mf][2] = __float_as_uint(As_lo[r * AS_STRIDE + c + 4]);
                alo[mf][3] = __float_as_uint(As_lo[(r + 8) * AS_STRIDE + c + 4]);
            }
#pragma unroll
            for (int nf = 0; nf < 8; nf++) {
                uint32_t bhi[2], blo[2];
                int n = n_off + nf * 8 + gq;
                int c = ks + tg;
                bhi[0] = __float_as_uint(Ws_hi[n * AS_STRIDE + c]);
                bhi[1] = __float_as_uint(Ws_hi[n * AS_STRIDE + c + 4]);
                blo[0] = __float_as_uint(Ws_lo[n * AS_STRIDE + c]);
                blo[1] = __float_as_uint(Ws_lo[n * AS_STRIDE + c + 4]);
#pragma unroll
                for (int mf = 0; mf < 2; mf++) {
                    MMA_TF32(acc[mf][nf], ahi[mf], bhi);
                    MMA_TF32(acc[mf][nf], ahi[mf], blo);
                    MMA_TF32(acc[mf][nf], alo[mf], bhi);
                }
            }
        }
        __syncthreads();
    }

    float* dst = g_Wh + (size_t)et * N_NODES * OUT_SIZE;
#pragma unroll
    for (int mf = 0; mf < 2; mf++) {
#pragma unroll
        for (int nf = 0; nf < 8; nf++) {
            int row = m0 + m_off + mf * 16 + gq;
            int col = n_off + nf * 8 + tg * 2;
            if (row < N_NODES) {
                *(float2*)&dst[(size_t)row * OUT_SIZE + col] =
                    make_float2(acc[mf][nf][0], acc[mf][nf][1]);
            }
            if (row + 8 < N_NODES) {
                *(float2*)&dst[(size_t)(row + 8) * OUT_SIZE + col] =
                    make_float2(acc[mf][nf][2], acc[mf][nf][3]);
            }
        }
    }
}

// ---------------------------------------------------------------------------
// Gather + mean + bias: one warp per (node, etype), 8-deep MLP, dual acc.
// ---------------------------------------------------------------------------
__global__ __launch_bounds__(256) void gather_kernel(float* __restrict__ out,
                                                     const float* __restrict__ b) {
    const int et = blockIdx.y;
    const int wid = threadIdx.x >> 5;
    const int lane = threadIdx.x & 31;
    const int n = blockIdx.x * 8 + wid;
    if (n >= N_NODES) return;

    const int base = et * N_NODES + n;
    const int beg = __ldg(&g_off[base]);
    const int end = __ldg(&g_off[base + 1]);

    const float* wh = g_Wh + (size_t)et * N_NODES * OUT_SIZE;
    float4 a0 = make_float4(0.f, 0.f, 0.f, 0.f);
    float4 a1 = make_float4(0.f, 0.f, 0.f, 0.f);

    int j = beg;
    for (; j + 8 <= end; j += 8) {
        int s0 = __ldg(&g_eidx[j + 0]);
        int s1 = __ldg(&g_eidx[j + 1]);
        int s2 = __ldg(&g_eidx[j + 2]);
        int s3 = __ldg(&g_eidx[j + 3]);
        int s4 = __ldg(&g_eidx[j + 4]);
        int s5 = __ldg(&g_eidx[j + 5]);
        int s6 = __ldg(&g_eidx[j + 6]);
        int s7 = __ldg(&g_eidx[j + 7]);
        float4 v0 = __ldg((const float4*)&wh[(size_t)s0 * OUT_SIZE + lane * 4]);
        float4 v1 = __ldg((const float4*)&wh[(size_t)s1 * OUT_SIZE + lane * 4]);
        float4 v2 = __ldg((const float4*)&wh[(size_t)s2 * OUT_SIZE + lane * 4]);
        float4 v3 = __ldg((const float4*)&wh[(size_t)s3 * OUT_SIZE + lane * 4]);
        float4 v4 = __ldg((const float4*)&wh[(size_t)s4 * OUT_SIZE + lane * 4]);
        float4 v5 = __ldg((const float4*)&wh[(size_t)s5 * OUT_SIZE + lane * 4]);
        float4 v6 = __ldg((const float4*)&wh[(size_t)s6 * OUT_SIZE + lane * 4]);
        float4 v7 = __ldg((const float4*)&wh[(size_t)s7 * OUT_SIZE + lane * 4]);
        a0.x += v0.x + v1.x + v2.x + v3.x;
        a0.y += v0.y + v1.y + v2.y + v3.y;
        a0.z += v0.z + v1.z + v2.z + v3.z;
        a0.w += v0.w + v1.w + v2.w + v3.w;
        a1.x += v4.x + v5.x + v6.x + v7.x;
        a1.y += v4.y + v5.y + v6.y + v7.y;
        a1.z += v4.z + v5.z + v6.z + v7.z;
        a1.w += v4.w + v5.w + v6.w + v7.w;
    }
    for (; j < end; j++) {
        int s = __ldg(&g_eidx[j]);
        float4 v = __ldg((const float4*)&wh[(size_t)s * OUT_SIZE + lane * 4]);
        a0.x += v.x; a0.y += v.y; a0.z += v.z; a0.w += v.w;
    }
    a0.x += a1.x; a0.y += a1.y; a0.z += a1.z; a0.w += a1.w;

    float4 r;
    int cnt = end - beg;
    if (cnt > 0) {
        float inv = 1.0f / (float)cnt;
        float4 bb = __ldg(&((const float4*)b)[et * 32 + lane]);
        r.x = a0.x * inv + bb.x;
        r.y = a0.y * inv + bb.y;
        r.z = a0.z * inv + bb.z;
        r.w = a0.w * inv + bb.w;
    } else {
        r = make_float4(0.f, 0.f, 0.f, 0.f);
    }
    ((float4*)out)[((size_t)n * N_ET + et) * 32 + lane] = r;
}

// ---------------------------------------------------------------------------
extern "C" void kernel_launch(void* const* d_in, const int* in_sizes, int n_in,
                              void* d_out, int out_size) {
    const float* x    = (const float*)d_in[0];
    const int*   esrc = (const int*)d_in[1];
    const int*   edst = (const int*)d_in[2];
    const float* W    = (const float*)d_in[3];
    const float* b    = (const float*)d_in[4];
    float* out = (float*)d_out;

    hist_kernel<<<(TOTAL_E / 4 + 255) / 256, 256>>>(edst);
    scan_a_kernel<<<SCAN_BLOCKS, 256>>>();
    scan_b_kernel<<<1, 128>>>();
    scan_c_kernel<<<(N_TOT + 255) / 256, 256>>>();
    gemm_fill_kernel<<<FUSED_BLOCKS, 256>>>(x, W, esrc, edst);
    gather_kernel<<<dim3((N_NODES + 7) / 8, N_ET), 256>>>(out, b);
}

// round 5
// speedup vs baseline: 1.0652x; 1.0652x over previous
#include <cuda_runtime.h>
#include <cuda_bf16.h>
#include <stdint.h>

#define N_NODES 50000
#define N_EDGES 1000000
#define IN_SIZE 256
#define OUT_SIZE 128
#define N_ET 3
#define N_TOT (N_ET * N_NODES)          // 150000
#define TOTAL_E (N_ET * N_EDGES)        // 3000000
#define SCAN_CHUNK 2048
#define SCAN_BLOCKS ((N_TOT + SCAN_CHUNK - 1) / SCAN_CHUNK)   // 74

// Scratch
__device__ float g_Wh[(size_t)N_ET * N_NODES * OUT_SIZE];     // 76.8 MB
__device__ int   g_cnt[N_TOT];          // zeroed by scan_a after use -> stays zero
__device__ int   g_off[N_TOT + 1];
__device__ int   g_pos[N_TOT];
__device__ int   g_part[SCAN_BLOCKS];
__device__ int   g_eidx[TOTAL_E];       // src node per edge, dst-sorted

// ---------------------------------------------------------------------------
// CSR build
// ---------------------------------------------------------------------------
__global__ void hist_kernel(const int* __restrict__ edst) {
    int base = (blockIdx.x * blockDim.x + threadIdx.x) * 4;
    if (base >= TOTAL_E) return;
    if (base + 4 <= TOTAL_E) {
        int4 d4 = *(const int4*)&edst[base];
        int et0 = base / N_EDGES;
        int et3 = (base + 3) / N_EDGES;
        if (et0 == et3) {
            int o = et0 * N_NODES;
            atomicAdd(&g_cnt[o + d4.x], 1);
            atomicAdd(&g_cnt[o + d4.y], 1);
            atomicAdd(&g_cnt[o + d4.z], 1);
            atomicAdd(&g_cnt[o + d4.w], 1);
        } else {
            atomicAdd(&g_cnt[((base + 0) / N_EDGES) * N_NODES + d4.x], 1);
            atomicAdd(&g_cnt[((base + 1) / N_EDGES) * N_NODES + d4.y], 1);
            atomicAdd(&g_cnt[((base + 2) / N_EDGES) * N_NODES + d4.z], 1);
            atomicAdd(&g_cnt[((base + 3) / N_EDGES) * N_NODES + d4.w], 1);
        }
    } else {
        for (int i = base; i < TOTAL_E; i++)
            atomicAdd(&g_cnt[(i / N_EDGES) * N_NODES + __ldg(&edst[i])], 1);
    }
}

__global__ __launch_bounds__(256) void scan_a_kernel() {
    __shared__ int s[256];
    const int tid = threadIdx.x;
    const int base = blockIdx.x * SCAN_CHUNK + tid * 8;
    int v[8];
    int tsum = 0;
#pragma unroll
    for (int k = 0; k < 8; k++) {
        int i = base + k;
        v[k] = (i < N_TOT) ? g_cnt[i] : 0;
        if (i < N_TOT) g_cnt[i] = 0;        // leave zeroed for next replay
        tsum += v[k];
    }
    s[tid] = tsum;
    __syncthreads();
    for (int off = 1; off < 256; off <<= 1) {
        int t = (tid >= off) ? s[tid - off] : 0;
        __syncthreads();
        s[tid] += t;
        __syncthreads();
    }
    int run = s[tid] - tsum;
#pragma unroll
    for (int k = 0; k < 8; k++) {
        int i = base + k;
        if (i < N_TOT) g_off[i] = run;
        run += v[k];
    }
    if (tid == 255) g_part[blockIdx.x] = s[255];
}

__global__ __launch_bounds__(128) void scan_b_kernel() {
    __shared__ int s[128];
    int tid = threadIdx.x;
    int v = (tid < SCAN_BLOCKS) ? g_part[tid] : 0;
    s[tid] = v;
    __syncthreads();
    for (int off = 1; off < 128; off <<= 1) {
        int t = (tid >= off) ? s[tid - off] : 0;
        __syncthreads();
        s[tid] += t;
        __syncthreads();
    }
    if (tid < SCAN_BLOCKS) g_part[tid] = s[tid] - v;   // exclusive
    if (tid == 127) g_off[N_TOT] = s[127];
}

__global__ void scan_c_kernel() {
    int i = blockIdx.x * blockDim.x + threadIdx.x;
    if (i >= N_TOT) return;
    int o = g_off[i] + g_part[i / SCAN_CHUNK];
    g_off[i] = o;
    g_pos[i] = o;
}

__global__ void fill_kernel(const int* __restrict__ esrc,
                            const int* __restrict__ edst) {
    int base = (blockIdx.x * blockDim.x + threadIdx.x) * 4;
#pragma unroll
    for (int k = 0; k < 4; k++) {
        int i = base + k;
        if (i < TOTAL_E) {
            int et = i / N_EDGES;
            int d = __ldg(&edst[i]);
            int s = __ldg(&esrc[i]);
            int p = atomicAdd(&g_pos[et * N_NODES + d], 1);
            g_eidx[p] = s;
        }
    }
}

// ---------------------------------------------------------------------------
// TF32 helpers
// ---------------------------------------------------------------------------
__device__ __forceinline__ float tf32_rna(float x) {
    uint32_t u;
    asm("cvt.rna.tf32.f32 %0, %1;" : "=r"(u) : "f"(x));
    return __uint_as_float(u);
}

#define MMA_TF32(D, A, B)                                                     \
    asm volatile(                                                             \
        "mma.sync.aligned.m16n8k8.row.col.f32.tf32.tf32.f32 "                 \
        "{%0,%1,%2,%3}, {%4,%5,%6,%7}, {%8,%9}, {%0,%1,%2,%3};"               \
        : "+f"(D[0]), "+f"(D[1]), "+f"(D[2]), "+f"(D[3])                      \
        : "r"(A[0]), "r"(A[1]), "r"(A[2]), "r"(A[3]), "r"(B[0]), "r"(B[1]))

#define AS_STRIDE 20

__global__ __launch_bounds__(256, 1) void gemm_kernel(const float* __restrict__ x,
                                                      const float* __restrict__ W) {
    const int et = blockIdx.y;
    const int m0 = blockIdx.x * 128;
    const int tid = threadIdx.x;
    const int wid = tid >> 5;
    const int lane = tid & 31;
    const int m_off = (wid >> 1) * 32;
    const int n_off = (wid & 1) * 64;
    const int gq = lane >> 2;
    const int tg = lane & 3;

    __shared__ float As_hi[128 * AS_STRIDE];
    __shared__ float As_lo[128 * AS_STRIDE];
    __shared__ float Ws_hi[128 * AS_STRIDE];
    __shared__ float Ws_lo[128 * AS_STRIDE];

    const float* Wt = W + (size_t)et * IN_SIZE * OUT_SIZE;

    float acc[2][8][4];
#pragma unroll
    for (int i = 0; i < 2; i++)
#pragma unroll
        for (int j = 0; j < 8; j++)
#pragma unroll
            for (int c = 0; c < 4; c++) acc[i][j][c] = 0.0f;

    for (int k0 = 0; k0 < IN_SIZE; k0 += 16) {
#pragma unroll
        for (int i = 0; i < 2; i++) {
            int f4 = tid + i * 256;
            int row = f4 >> 2;
            int kc = (f4 & 3) * 4;
            int gm = m0 + row;
            float4 v = make_float4(0.f, 0.f, 0.f, 0.f);
            if (gm < N_NODES) v = *(const float4*)&x[(size_t)gm * IN_SIZE + k0 + kc];
            float4 h, l;
            h.x = tf32_rna(v.x); l.x = tf32_rna(v.x - h.x);
            h.y = tf32_rna(v.y); l.y = tf32_rna(v.y - h.y);
            h.z = tf32_rna(v.z); l.z = tf32_rna(v.z - h.z);
            h.w = tf32_rna(v.w); l.w = tf32_rna(v.w - h.w);
            *(float4*)&As_hi[row * AS_STRIDE + kc] = h;
            *(float4*)&As_lo[row * AS_STRIDE + kc] = l;
        }
#pragma unroll
        for (int i = 0; i < 2; i++) {
            int f4 = tid + i * 256;
            int kr = f4 >> 5;
            int nc = (f4 & 31) * 4;
            float4 v = *(const float4*)&Wt[(size_t)(k0 + kr) * OUT_SIZE + nc];
            float h, l;
            h = tf32_rna(v.x); l = tf32_rna(v.x - h);
            Ws_hi[(nc + 0) * AS_STRIDE + kr] = h; Ws_lo[(nc + 0) * AS_STRIDE + kr] = l;
            h = tf32_rna(v.y); l = tf32_rna(v.y - h);
            Ws_hi[(nc + 1) * AS_STRIDE + kr] = h; Ws_lo[(nc + 1) * AS_STRIDE + kr] = l;
            h = tf32_rna(v.z); l = tf32_rna(v.z - h);
            Ws_hi[(nc + 2) * AS_STRIDE + kr] = h; Ws_lo[(nc + 2) * AS_STRIDE + kr] = l;
            h = tf32_rna(v.w); l = tf32_rna(v.w - h);
            Ws_hi[(nc + 3) * AS_STRIDE + kr] = h; Ws_lo[(nc + 3) * AS_STRIDE + kr] = l;
        }
        __syncthreads();

#pragma unroll
        for (int ks = 0; ks < 16; ks += 8) {
            uint32_t ahi[2][4], alo[2][4];
#pragma unroll
            for (int mf = 0; mf < 2; mf++) {
                int r = m_off + mf * 16 + gq;
                int c = ks + tg;
                ahi[mf][0] = __float_as_uint(As_hi[r * AS_STRIDE + c]);
                ahi[mf][1] = __float_as_uint(As_hi[(r + 8) * AS_STRIDE + c]);
                ahi[mf][2] = __float_as_uint(As_hi[r * AS_STRIDE + c + 4]);
                ahi[mf][3] = __float_as_uint(As_hi[(r + 8) * AS_STRIDE + c + 4]);
                alo[mf][0] = __float_as_uint(As_lo[r * AS_STRIDE + c]);
                alo[mf][1] = __float_as_uint(As_lo[(r + 8) * AS_STRIDE + c]);
                alo[mf][2] = __float_as_uint(As_lo[r * AS_STRIDE + c + 4]);
                alo[mf][3] = __float_as_uint(As_lo[(r + 8) * AS_STRIDE + c + 4]);
            }
#pragma unroll
            for (int nf = 0; nf < 8; nf++) {
                uint32_t bhi[2], blo[2];
                int n = n_off + nf * 8 + gq;
                int c = ks + tg;
                bhi[0] = __float_as_uint(Ws_hi[n * AS_STRIDE + c]);
                bhi[1] = __float_as_uint(Ws_hi[n * AS_STRIDE + c + 4]);
                blo[0] = __float_as_uint(Ws_lo[n * AS_STRIDE + c]);
                blo[1] = __float_as_uint(Ws_lo[n * AS_STRIDE + c + 4]);
#pragma unroll
                for (int mf = 0; mf < 2; mf++) {
                    MMA_TF32(acc[mf][nf], ahi[mf], bhi);
                    MMA_TF32(acc[mf][nf], ahi[mf], blo);
                    MMA_TF32(acc[mf][nf], alo[mf], bhi);
                }
            }
        }
        __syncthreads();
    }

    float* dst = g_Wh + (size_t)et * N_NODES * OUT_SIZE;
#pragma unroll
    for (int mf = 0; mf < 2; mf++) {
#pragma unroll
        for (int nf = 0; nf < 8; nf++) {
            int row = m0 + m_off + mf * 16 + gq;
            int col = n_off + nf * 8 + tg * 2;
            if (row < N_NODES) {
                *(float2*)&dst[(size_t)row * OUT_SIZE + col] =
                    make_float2(acc[mf][nf][0], acc[mf][nf][1]);
            }
            if (row + 8 < N_NODES) {
                *(float2*)&dst[(size_t)(row + 8) * OUT_SIZE + col] =
                    make_float2(acc[mf][nf][2], acc[mf][nf][3]);
            }
        }
    }
}

// ---------------------------------------------------------------------------
// Gather + mean + bias: one warp per (node, etype), 8-deep MLP, dual acc.
// ---------------------------------------------------------------------------
__global__ __launch_bounds__(256) void gather_kernel(float* __restrict__ out,
                                                     const float* __restrict__ b) {
    const int et = blockIdx.y;
    const int wid = threadIdx.x >> 5;
    const int lane = threadIdx.x & 31;
    const int n = blockIdx.x * 8 + wid;
    if (n >= N_NODES) return;

    const int base = et * N_NODES + n;
    const int beg = __ldg(&g_off[base]);
    const int end = __ldg(&g_off[base + 1]);

    const float* wh = g_Wh + (size_t)et * N_NODES * OUT_SIZE;
    float4 a0 = make_float4(0.f, 0.f, 0.f, 0.f);
    float4 a1 = make_float4(0.f, 0.f, 0.f, 0.f);

    int j = beg;
    for (; j + 8 <= end; j += 8) {
        int s0 = __ldg(&g_eidx[j + 0]);
        int s1 = __ldg(&g_eidx[j + 1]);
        int s2 = __ldg(&g_eidx[j + 2]);
        int s3 = __ldg(&g_eidx[j + 3]);
        int s4 = __ldg(&g_eidx[j + 4]);
        int s5 = __ldg(&g_eidx[j + 5]);
        int s6 = __ldg(&g_eidx[j + 6]);
        int s7 = __ldg(&g_eidx[j + 7]);
        float4 v0 = __ldg((const float4*)&wh[(size_t)s0 * OUT_SIZE + lane * 4]);
        float4 v1 = __ldg((const float4*)&wh[(size_t)s1 * OUT_SIZE + lane * 4]);
        float4 v2 = __ldg((const float4*)&wh[(size_t)s2 * OUT_SIZE + lane * 4]);
        float4 v3 = __ldg((const float4*)&wh[(size_t)s3 * OUT_SIZE + lane * 4]);
        float4 v4 = __ldg((const float4*)&wh[(size_t)s4 * OUT_SIZE + lane * 4]);
        float4 v5 = __ldg((const float4*)&wh[(size_t)s5 * OUT_SIZE + lane * 4]);
        float4 v6 = __ldg((const float4*)&wh[(size_t)s6 * OUT_SIZE + lane * 4]);
        float4 v7 = __ldg((const float4*)&wh[(size_t)s7 * OUT_SIZE + lane * 4]);
        a0.x += v0.x + v1.x + v2.x + v3.x;
        a0.y += v0.y + v1.y + v2.y + v3.y;
        a0.z += v0.z + v1.z + v2.z + v3.z;
        a0.w += v0.w + v1.w + v2.w + v3.w;
        a1.x += v4.x + v5.x + v6.x + v7.x;
        a1.y += v4.y + v5.y + v6.y + v7.y;
        a1.z += v4.z + v5.z + v6.z + v7.z;
        a1.w += v4.w + v5.w + v6.w + v7.w;
    }
    for (; j < end; j++) {
        int s = __ldg(&g_eidx[j]);
        float4 v = __ldg((const float4*)&wh[(size_t)s * OUT_SIZE + lane * 4]);
        a0.x += v.x; a0.y += v.y; a0.z += v.z; a0.w += v.w;
    }
    a0.x += a1.x; a0.y += a1.y; a0.z += a1.z; a0.w += a1.w;

    float4 r;
    int cnt = end - beg;
    if (cnt > 0) {
        float inv = 1.0f / (float)cnt;
        float4 bb = __ldg(&((const float4*)b)[et * 32 + lane]);
        r.x = a0.x * inv + bb.x;
        r.y = a0.y * inv + bb.y;
        r.z = a0.z * inv + bb.z;
        r.w = a0.w * inv + bb.w;
    } else {
        r = make_float4(0.f, 0.f, 0.f, 0.f);
    }
    ((float4*)out)[((size_t)n * N_ET + et) * 32 + lane] = r;
}

// ---------------------------------------------------------------------------
// Two-stream fork/join: CSR chain overlaps the GEMM. Stream/event handles are
// created once (host-side resources only; the captured GPU work is identical
// on every call).
// ---------------------------------------------------------------------------
extern "C" void kernel_launch(void* const* d_in, const int* in_sizes, int n_in,
                              void* d_out, int out_size) {
    const float* x    = (const float*)d_in[0];
    const int*   esrc = (const int*)d_in[1];
    const int*   edst = (const int*)d_in[2];
    const float* W    = (const float*)d_in[3];
    const float* b    = (const float*)d_in[4];
    float* out = (float*)d_out;

    static cudaStream_t s_csr = nullptr;
    static cudaEvent_t ev_fork = nullptr, ev_join = nullptr;
    if (s_csr == nullptr) {
        cudaStreamCreateWithFlags(&s_csr, cudaStreamNonBlocking);
        cudaEventCreateWithFlags(&ev_fork, cudaEventDisableTiming);
        cudaEventCreateWithFlags(&ev_join, cudaEventDisableTiming);
    }

    // Fork: CSR build chain on s_csr, GEMM on the launch (capture-origin) stream.
    cudaEventRecord(ev_fork, 0);
    cudaStreamWaitEvent(s_csr, ev_fork, 0);

    hist_kernel<<<(TOTAL_E / 4 + 255) / 256, 256, 0, s_csr>>>(edst);
    scan_a_kernel<<<SCAN_BLOCKS, 256, 0, s_csr>>>();
    scan_b_kernel<<<1, 128, 0, s_csr>>>();
    scan_c_kernel<<<(N_TOT + 255) / 256, 256, 0, s_csr>>>();
    fill_kernel<<<(TOTAL_E / 4 + 255) / 256, 256, 0, s_csr>>>(esrc, edst);
    cudaEventRecord(ev_join, s_csr);

    dim3 ggrid((N_NODES + 127) / 128, N_ET);
    gemm_kernel<<<ggrid, 256>>>(x, W);

    // Join: gather needs both g_Wh (stream 0) and the CSR arrays (s_csr).
    cudaStreamWaitEvent(0, ev_join, 0);
    gather_kernel<<<dim3((N_NODES + 7) / 8, N_ET), 256>>>(out, b);
}

// round 6
// speedup vs baseline: 1.1269x; 1.0580x over previous
#include <cuda_runtime.h>
#include <cuda_bf16.h>
#include <cuda_fp16.h>
#include <stdint.h>

#define N_NODES 50000
#define N_EDGES 1000000
#define IN_SIZE 256
#define OUT_SIZE 128
#define N_ET 3
#define N_TOT (N_ET * N_NODES)          // 150000
#define TOTAL_E (N_ET * N_EDGES)        // 3000000
#define SCAN_CHUNK 2048
#define SCAN_BLOCKS ((N_TOT + SCAN_CHUNK - 1) / SCAN_CHUNK)   // 74

// Scratch: Wh stored in fp16 (halves gather traffic; fully L2-resident 38.4MB)
__device__ __half g_Wh[(size_t)N_ET * N_NODES * OUT_SIZE];
__device__ int   g_cnt[N_TOT];          // zeroed by scan_a after use -> stays zero
__device__ int   g_off[N_TOT + 1];
__device__ int   g_pos[N_TOT];
__device__ int   g_part[SCAN_BLOCKS];
__device__ int   g_eidx[TOTAL_E];       // src node per edge, dst-sorted

// ---------------------------------------------------------------------------
// CSR build
// ---------------------------------------------------------------------------
__global__ void hist_kernel(const int* __restrict__ edst) {
    int base = (blockIdx.x * blockDim.x + threadIdx.x) * 4;
    if (base >= TOTAL_E) return;
    if (base + 4 <= TOTAL_E) {
        int4 d4 = *(const int4*)&edst[base];
        int et0 = base / N_EDGES;
        int et3 = (base + 3) / N_EDGES;
        if (et0 == et3) {
            int o = et0 * N_NODES;
            atomicAdd(&g_cnt[o + d4.x], 1);
            atomicAdd(&g_cnt[o + d4.y], 1);
            atomicAdd(&g_cnt[o + d4.z], 1);
            atomicAdd(&g_cnt[o + d4.w], 1);
        } else {
            atomicAdd(&g_cnt[((base + 0) / N_EDGES) * N_NODES + d4.x], 1);
            atomicAdd(&g_cnt[((base + 1) / N_EDGES) * N_NODES + d4.y], 1);
            atomicAdd(&g_cnt[((base + 2) / N_EDGES) * N_NODES + d4.z], 1);
            atomicAdd(&g_cnt[((base + 3) / N_EDGES) * N_NODES + d4.w], 1);
        }
    } else {
        for (int i = base; i < TOTAL_E; i++)
            atomicAdd(&g_cnt[(i / N_EDGES) * N_NODES + __ldg(&edst[i])], 1);
    }
}

__global__ __launch_bounds__(256) void scan_a_kernel() {
    __shared__ int s[256];
    const int tid = threadIdx.x;
    const int base = blockIdx.x * SCAN_CHUNK + tid * 8;
    int v[8];
    int tsum = 0;
#pragma unroll
    for (int k = 0; k < 8; k++) {
        int i = base + k;
        v[k] = (i < N_TOT) ? g_cnt[i] : 0;
        if (i < N_TOT) g_cnt[i] = 0;        // leave zeroed for next replay
        tsum += v[k];
    }
    s[tid] = tsum;
    __syncthreads();
    for (int off = 1; off < 256; off <<= 1) {
        int t = (tid >= off) ? s[tid - off] : 0;
        __syncthreads();
        s[tid] += t;
        __syncthreads();
    }
    int run = s[tid] - tsum;
#pragma unroll
    for (int k = 0; k < 8; k++) {
        int i = base + k;
        if (i < N_TOT) g_off[i] = run;
        run += v[k];
    }
    if (tid == 255) g_part[blockIdx.x] = s[255];
}

__global__ __launch_bounds__(128) void scan_b_kernel() {
    __shared__ int s[128];
    int tid = threadIdx.x;
    int v = (tid < SCAN_BLOCKS) ? g_part[tid] : 0;
    s[tid] = v;
    __syncthreads();
    for (int off = 1; off < 128; off <<= 1) {
        int t = (tid >= off) ? s[tid - off] : 0;
        __syncthreads();
        s[tid] += t;
        __syncthreads();
    }
    if (tid < SCAN_BLOCKS) g_part[tid] = s[tid] - v;   // exclusive
    if (tid == 127) g_off[N_TOT] = s[127];
}

__global__ void scan_c_kernel() {
    int i = blockIdx.x * blockDim.x + threadIdx.x;
    if (i >= N_TOT) return;
    int o = g_off[i] + g_part[i / SCAN_CHUNK];
    g_off[i] = o;
    g_pos[i] = o;
}

__global__ void fill_kernel(const int* __restrict__ esrc,
                            const int* __restrict__ edst) {
    int base = (blockIdx.x * blockDim.x + threadIdx.x) * 4;
#pragma unroll
    for (int k = 0; k < 4; k++) {
        int i = base + k;
        if (i < TOTAL_E) {
            int et = i / N_EDGES;
            int d = __ldg(&edst[i]);
            int s = __ldg(&esrc[i]);
            int p = atomicAdd(&g_pos[et * N_NODES + d], 1);
            g_eidx[p] = s;
        }
    }
}

// ---------------------------------------------------------------------------
// TF32 helpers
// ---------------------------------------------------------------------------
__device__ __forceinline__ float tf32_rna(float x) {
    uint32_t u;
    asm("cvt.rna.tf32.f32 %0, %1;" : "=r"(u) : "f"(x));
    return __uint_as_float(u);
}

#define MMA_TF32(D, A, B)                                                     \
    asm volatile(                                                             \
        "mma.sync.aligned.m16n8k8.row.col.f32.tf32.tf32.f32 "                 \
        "{%0,%1,%2,%3}, {%4,%5,%6,%7}, {%8,%9}, {%0,%1,%2,%3};"               \
        : "+f"(D[0]), "+f"(D[1]), "+f"(D[2]), "+f"(D[3])                      \
        : "r"(A[0]), "r"(A[1]), "r"(A[2]), "r"(A[3]), "r"(B[0]), "r"(B[1]))

#define AS_STRIDE 20

__global__ __launch_bounds__(256, 1) void gemm_kernel(const float* __restrict__ x,
                                                      const float* __restrict__ W) {
    const int et = blockIdx.y;
    const int m0 = blockIdx.x * 128;
    const int tid = threadIdx.x;
    const int wid = tid >> 5;
    const int lane = tid & 31;
    const int m_off = (wid >> 1) * 32;
    const int n_off = (wid & 1) * 64;
    const int gq = lane >> 2;
    const int tg = lane & 3;

    __shared__ float As_hi[128 * AS_STRIDE];
    __shared__ float As_lo[128 * AS_STRIDE];
    __shared__ float Ws_hi[128 * AS_STRIDE];
    __shared__ float Ws_lo[128 * AS_STRIDE];

    const float* Wt = W + (size_t)et * IN_SIZE * OUT_SIZE;

    float acc[2][8][4];
#pragma unroll
    for (int i = 0; i < 2; i++)
#pragma unroll
        for (int j = 0; j < 8; j++)
#pragma unroll
            for (int c = 0; c < 4; c++) acc[i][j][c] = 0.0f;

    for (int k0 = 0; k0 < IN_SIZE; k0 += 16) {
#pragma unroll
        for (int i = 0; i < 2; i++) {
            int f4 = tid + i * 256;
            int row = f4 >> 2;
            int kc = (f4 & 3) * 4;
            int gm = m0 + row;
            float4 v = make_float4(0.f, 0.f, 0.f, 0.f);
            if (gm < N_NODES) v = *(const float4*)&x[(size_t)gm * IN_SIZE + k0 + kc];
            float4 h, l;
            h.x = tf32_rna(v.x); l.x = tf32_rna(v.x - h.x);
            h.y = tf32_rna(v.y); l.y = tf32_rna(v.y - h.y);
            h.z = tf32_rna(v.z); l.z = tf32_rna(v.z - h.z);
            h.w = tf32_rna(v.w); l.w = tf32_rna(v.w - h.w);
            *(float4*)&As_hi[row * AS_STRIDE + kc] = h;
            *(float4*)&As_lo[row * AS_STRIDE + kc] = l;
        }
#pragma unroll
        for (int i = 0; i < 2; i++) {
            int f4 = tid + i * 256;
            int kr = f4 >> 5;
            int nc = (f4 & 31) * 4;
            float4 v = *(const float4*)&Wt[(size_t)(k0 + kr) * OUT_SIZE + nc];
            float h, l;
            h = tf32_rna(v.x); l = tf32_rna(v.x - h);
            Ws_hi[(nc + 0) * AS_STRIDE + kr] = h; Ws_lo[(nc + 0) * AS_STRIDE + kr] = l;
            h = tf32_rna(v.y); l = tf32_rna(v.y - h);
            Ws_hi[(nc + 1) * AS_STRIDE + kr] = h; Ws_lo[(nc + 1) * AS_STRIDE + kr] = l;
            h = tf32_rna(v.z); l = tf32_rna(v.z - h);
            Ws_hi[(nc + 2) * AS_STRIDE + kr] = h; Ws_lo[(nc + 2) * AS_STRIDE + kr] = l;
            h = tf32_rna(v.w); l = tf32_rna(v.w - h);
            Ws_hi[(nc + 3) * AS_STRIDE + kr] = h; Ws_lo[(nc + 3) * AS_STRIDE + kr] = l;
        }
        __syncthreads();

#pragma unroll
        for (int ks = 0; ks < 16; ks += 8) {
            uint32_t ahi[2][4], alo[2][4];
#pragma unroll
            for (int mf = 0; mf < 2; mf++) {
                int r = m_off + mf * 16 + gq;
                int c = ks + tg;
                ahi[mf][0] = __float_as_uint(As_hi[r * AS_STRIDE + c]);
                ahi[mf][1] = __float_as_uint(As_hi[(r + 8) * AS_STRIDE + c]);
                ahi[mf][2] = __float_as_uint(As_hi[r * AS_STRIDE + c + 4]);
                ahi[mf][3] = __float_as_uint(As_hi[(r + 8) * AS_STRIDE + c + 4]);
                alo[mf][0] = __float_as_uint(As_lo[r * AS_STRIDE + c]);
                alo[mf][1] = __float_as_uint(As_lo[(r + 8) * AS_STRIDE + c]);
                alo[mf][2] = __float_as_uint(As_lo[r * AS_STRIDE + c + 4]);
                alo[mf][3] = __float_as_uint(As_lo[(r + 8) * AS_STRIDE + c + 4]);
            }
#pragma unroll
            for (int nf = 0; nf < 8; nf++) {
                uint32_t bhi[2], blo[2];
                int n = n_off + nf * 8 + gq;
                int c = ks + tg;
                bhi[0] = __float_as_uint(Ws_hi[n * AS_STRIDE + c]);
                bhi[1] = __float_as_uint(Ws_hi[n * AS_STRIDE + c + 4]);
                blo[0] = __float_as_uint(Ws_lo[n * AS_STRIDE + c]);
                blo[1] = __float_as_uint(Ws_lo[n * AS_STRIDE + c + 4]);
#pragma unroll
                for (int mf = 0; mf < 2; mf++) {
                    MMA_TF32(acc[mf][nf], ahi[mf], bhi);
                    MMA_TF32(acc[mf][nf], ahi[mf], blo);
                    MMA_TF32(acc[mf][nf], alo[mf], bhi);
                }
            }
        }
        __syncthreads();
    }

    // epilogue: write Wh as fp16 (half2 pairs)
    __half* dst = g_Wh + (size_t)et * N_NODES * OUT_SIZE;
#pragma unroll
    for (int mf = 0; mf < 2; mf++) {
#pragma unroll
        for (int nf = 0; nf < 8; nf++) {
            int row = m0 + m_off + mf * 16 + gq;
            int col = n_off + nf * 8 + tg * 2;
            if (row < N_NODES) {
                *(__half2*)&dst[(size_t)row * OUT_SIZE + col] =
                    __floats2half2_rn(acc[mf][nf][0], acc[mf][nf][1]);
            }
            if (row + 8 < N_NODES) {
                *(__half2*)&dst[(size_t)(row + 8) * OUT_SIZE + col] =
                    __floats2half2_rn(acc[mf][nf][2], acc[mf][nf][3]);
            }
        }
    }
}

// ---------------------------------------------------------------------------
// Gather + mean + bias: one warp per (node, etype); lane owns 4 channels,
// loads them as one 8B uint2 (2x half2) per edge. 8-deep MLP, dual fp32 acc.
// ---------------------------------------------------------------------------
__global__ __launch_bounds__(256) void gather_kernel(float* __restrict__ out,
                                                     const float* __restrict__ b) {
    const int et = blockIdx.y;
    const int wid = threadIdx.x >> 5;
    const int lane = threadIdx.x & 31;
    const int n = blockIdx.x * 8 + wid;
    if (n >= N_NODES) return;

    const int base = et * N_NODES + n;
    const int beg = __ldg(&g_off[base]);
    const int end = __ldg(&g_off[base + 1]);

    const __half* wh = g_Wh + (size_t)et * N_NODES * OUT_SIZE;
    float4 a0 = make_float4(0.f, 0.f, 0.f, 0.f);
    float4 a1 = make_float4(0.f, 0.f, 0.f, 0.f);

    int j = beg;
    for (; j + 8 <= end; j += 8) {
        int s0 = __ldg(&g_eidx[j + 0]);
        int s1 = __ldg(&g_eidx[j + 1]);
        int s2 = __ldg(&g_eidx[j + 2]);
        int s3 = __ldg(&g_eidx[j + 3]);
        int s4 = __ldg(&g_eidx[j + 4]);
        int s5 = __ldg(&g_eidx[j + 5]);
        int s6 = __ldg(&g_eidx[j + 6]);
        int s7 = __ldg(&g_eidx[j + 7]);
        uint2 u0 = __ldg((const uint2*)&wh[(size_t)s0 * OUT_SIZE + lane * 4]);
        uint2 u1 = __ldg((const uint2*)&wh[(size_t)s1 * OUT_SIZE + lane * 4]);
        uint2 u2 = __ldg((const uint2*)&wh[(size_t)s2 * OUT_SIZE + lane * 4]);
        uint2 u3 = __ldg((const uint2*)&wh[(size_t)s3 * OUT_SIZE + lane * 4]);
        uint2 u4 = __ldg((const uint2*)&wh[(size_t)s4 * OUT_SIZE + lane * 4]);
        uint2 u5 = __ldg((const uint2*)&wh[(size_t)s5 * OUT_SIZE + lane * 4]);
        uint2 u6 = __ldg((const uint2*)&wh[(size_t)s6 * OUT_SIZE + lane * 4]);
        uint2 u7 = __ldg((const uint2*)&wh[(size_t)s7 * OUT_SIZE + lane * 4]);
#define ACC(A, U)                                                            \
        {                                                                    \
            float2 f0 = __half22float2(*(const __half2*)&U.x);               \
            float2 f1 = __half22float2(*(const __half2*)&U.y);               \
            A.x += f0.x; A.y += f0.y; A.z += f1.x; A.w += f1.y;              \
        }
        ACC(a0, u0) ACC(a0, u1) ACC(a0, u2) ACC(a0, u3)
        ACC(a1, u4) ACC(a1, u5) ACC(a1, u6) ACC(a1, u7)
    }
    for (; j < end; j++) {
        int s = __ldg(&g_eidx[j]);
        uint2 u = __ldg((const uint2*)&wh[(size_t)s * OUT_SIZE + lane * 4]);
        ACC(a0, u)
    }
#undef ACC
    a0.x += a1.x; a0.y += a1.y; a0.z += a1.z; a0.w += a1.w;

    float4 r;
    int cnt = end - beg;
    if (cnt > 0) {
        float inv = 1.0f / (float)cnt;
        float4 bb = __ldg(&((const float4*)b)[et * 32 + lane]);
        r.x = a0.x * inv + bb.x;
        r.y = a0.y * inv + bb.y;
        r.z = a0.z * inv + bb.z;
        r.w = a0.w * inv + bb.w;
    } else {
        r = make_float4(0.f, 0.f, 0.f, 0.f);
    }
    ((float4*)out)[((size_t)n * N_ET + et) * 32 + lane] = r;
}

// ---------------------------------------------------------------------------
// Two-stream fork/join: CSR chain overlaps the GEMM.
// ---------------------------------------------------------------------------
extern "C" void kernel_launch(void* const* d_in, const int* in_sizes, int n_in,
                              void* d_out, int out_size) {
    const float* x    = (const float*)d_in[0];
    const int*   esrc = (const int*)d_in[1];
    const int*   edst = (const int*)d_in[2];
    const float* W    = (const float*)d_in[3];
    const float* b    = (const float*)d_in[4];
    float* out = (float*)d_out;

    static cudaStream_t s_csr = nullptr;
    static cudaEvent_t ev_fork = nullptr, ev_join = nullptr;
    if (s_csr == nullptr) {
        cudaStreamCreateWithFlags(&s_csr, cudaStreamNonBlocking);
        cudaEventCreateWithFlags(&ev_fork, cudaEventDisableTiming);
        cudaEventCreateWithFlags(&ev_join, cudaEventDisableTiming);
    }

    cudaEventRecord(ev_fork, 0);
    cudaStreamWaitEvent(s_csr, ev_fork, 0);

    hist_kernel<<<(TOTAL_E / 4 + 255) / 256, 256, 0, s_csr>>>(edst);
    scan_a_kernel<<<SCAN_BLOCKS, 256, 0, s_csr>>>();
    scan_b_kernel<<<1, 128, 0, s_csr>>>();
    scan_c_kernel<<<(N_TOT + 255) / 256, 256, 0, s_csr>>>();
    fill_kernel<<<(TOTAL_E / 4 + 255) / 256, 256, 0, s_csr>>>(esrc, edst);
    cudaEventRecord(ev_join, s_csr);

    dim3 ggrid((N_NODES + 127) / 128, N_ET);
    gemm_kernel<<<ggrid, 256>>>(x, W);

    cudaStreamWaitEvent(0, ev_join, 0);
    gather_kernel<<<dim3((N_NODES + 7) / 8, N_ET), 256>>>(out, b);
}

// round 7
// speedup vs baseline: 1.3123x; 1.1645x over previous
#include <cuda_runtime.h>
#include <cuda_bf16.h>
#include <cuda_fp16.h>
#include <stdint.h>

#define N_NODES 50000
#define N_EDGES 1000000
#define IN_SIZE 256
#define OUT_SIZE 128
#define N_ET 3
#define N_TOT (N_ET * N_NODES)          // 150000
#define TOTAL_E (N_ET * N_EDGES)        // 3000000
#define SCAN_CHUNK 2048
#define SCAN_BLOCKS ((N_TOT + SCAN_CHUNK - 1) / SCAN_CHUNK)   // 74
#define GEMM_BX ((N_NODES + 127) / 128) // 391

// Scratch: Wh in fp16 (halves gather traffic; 38.4MB, L2-resident)
__device__ __half g_Wh[(size_t)N_ET * N_NODES * OUT_SIZE];
__device__ int   g_cnt[N_TOT];          // zeroed by scan_a after use -> stays zero
__device__ int   g_off[N_TOT + 1];
__device__ int   g_pos[N_TOT];
__device__ int   g_part[SCAN_BLOCKS];
__device__ int   g_eidx[TOTAL_E];       // src node per edge, dst-sorted

// ---------------------------------------------------------------------------
// CSR build
// ---------------------------------------------------------------------------
__global__ void hist_kernel(const int* __restrict__ edst) {
    int base = (blockIdx.x * blockDim.x + threadIdx.x) * 4;
    if (base >= TOTAL_E) return;
    if (base + 4 <= TOTAL_E) {
        int4 d4 = *(const int4*)&edst[base];
        int et0 = base / N_EDGES;
        int et3 = (base + 3) / N_EDGES;
        if (et0 == et3) {
            int o = et0 * N_NODES;
            atomicAdd(&g_cnt[o + d4.x], 1);
            atomicAdd(&g_cnt[o + d4.y], 1);
            atomicAdd(&g_cnt[o + d4.z], 1);
            atomicAdd(&g_cnt[o + d4.w], 1);
        } else {
            atomicAdd(&g_cnt[((base + 0) / N_EDGES) * N_NODES + d4.x], 1);
            atomicAdd(&g_cnt[((base + 1) / N_EDGES) * N_NODES + d4.y], 1);
            atomicAdd(&g_cnt[((base + 2) / N_EDGES) * N_NODES + d4.z], 1);
            atomicAdd(&g_cnt[((base + 3) / N_EDGES) * N_NODES + d4.w], 1);
        }
    } else {
        for (int i = base; i < TOTAL_E; i++)
            atomicAdd(&g_cnt[(i / N_EDGES) * N_NODES + __ldg(&edst[i])], 1);
    }
}

__global__ __launch_bounds__(256) void scan_a_kernel() {
    __shared__ int s[256];
    const int tid = threadIdx.x;
    const int base = blockIdx.x * SCAN_CHUNK + tid * 8;
    int v[8];
    int tsum = 0;
#pragma unroll
    for (int k = 0; k < 8; k++) {
        int i = base + k;
        v[k] = (i < N_TOT) ? g_cnt[i] : 0;
        if (i < N_TOT) g_cnt[i] = 0;        // leave zeroed for next replay
        tsum += v[k];
    }
    s[tid] = tsum;
    __syncthreads();
    for (int off = 1; off < 256; off <<= 1) {
        int t = (tid >= off) ? s[tid - off] : 0;
        __syncthreads();
        s[tid] += t;
        __syncthreads();
    }
    int run = s[tid] - tsum;
#pragma unroll
    for (int k = 0; k < 8; k++) {
        int i = base + k;
        if (i < N_TOT) g_off[i] = run;
        run += v[k];
    }
    if (tid == 255) g_part[blockIdx.x] = s[255];
}

__global__ __launch_bounds__(128) void scan_b_kernel() {
    __shared__ int s[128];
    int tid = threadIdx.x;
    int v = (tid < SCAN_BLOCKS) ? g_part[tid] : 0;
    s[tid] = v;
    __syncthreads();
    for (int off = 1; off < 128; off <<= 1) {
        int t = (tid >= off) ? s[tid - off] : 0;
        __syncthreads();
        s[tid] += t;
        __syncthreads();
    }
    if (tid < SCAN_BLOCKS) g_part[tid] = s[tid] - v;   // exclusive
    if (tid == 127) g_off[N_TOT] = s[127];
}

__global__ void scan_c_kernel() {
    int i = blockIdx.x * blockDim.x + threadIdx.x;
    if (i >= N_TOT) return;
    int o = g_off[i] + g_part[i / SCAN_CHUNK];
    g_off[i] = o;
    g_pos[i] = o;
}

__global__ void fill_kernel(const int* __restrict__ esrc,
                            const int* __restrict__ edst) {
    int base = (blockIdx.x * blockDim.x + threadIdx.x) * 4;
#pragma unroll
    for (int k = 0; k < 4; k++) {
        int i = base + k;
        if (i < TOTAL_E) {
            int et = i / N_EDGES;
            int d = __ldg(&edst[i]);
            int s = __ldg(&esrc[i]);
            int p = atomicAdd(&g_pos[et * N_NODES + d], 1);
            g_eidx[p] = s;
        }
    }
}

// ---------------------------------------------------------------------------
// TF32 helpers
// ---------------------------------------------------------------------------
__device__ __forceinline__ float tf32_rna(float x) {
    uint32_t u;
    asm("cvt.rna.tf32.f32 %0, %1;" : "=r"(u) : "f"(x));
    return __uint_as_float(u);
}

#define MMA_TF32(D, A, B)                                                     \
    asm volatile(                                                             \
        "mma.sync.aligned.m16n8k8.row.col.f32.tf32.tf32.f32 "                 \
        "{%0,%1,%2,%3}, {%4,%5,%6,%7}, {%8,%9}, {%0,%1,%2,%3};"               \
        : "+f"(D[0]), "+f"(D[1]), "+f"(D[2]), "+f"(D[3])                      \
        : "r"(A[0]), "r"(A[1]), "r"(A[2]), "r"(A[3]), "r"(B[0]), "r"(B[1]))

#define AS_STRIDE 20

// ---------------------------------------------------------------------------
// Per-etype GEMM: Wh[et] = x @ W[et], 2-pass TF32 (ahi*bhi + ahi*blo).
// Residual (alo*b ~ 2^-12 rel) is below the fp16 Wh storage error.
// ---------------------------------------------------------------------------
__global__ __launch_bounds__(256) void gemm_kernel(const float* __restrict__ x,
                                                   const float* __restrict__ W,
                                                   int et) {
    const int m0 = blockIdx.x * 128;
    const int tid = threadIdx.x;
    const int wid = tid >> 5;
    const int lane = tid & 31;
    const int m_off = (wid >> 1) * 32;
    const int n_off = (wid & 1) * 64;
    const int gq = lane >> 2;
    const int tg = lane & 3;

    __shared__ float As_hi[128 * AS_STRIDE];
    __shared__ float Ws_hi[128 * AS_STRIDE];   // [n][k]
    __shared__ float Ws_lo[128 * AS_STRIDE];

    const float* Wt = W + (size_t)et * IN_SIZE * OUT_SIZE;

    float acc[2][8][4];
#pragma unroll
    for (int i = 0; i < 2; i++)
#pragma unroll
        for (int j = 0; j < 8; j++)
#pragma unroll
            for (int c = 0; c < 4; c++) acc[i][j][c] = 0.0f;

    for (int k0 = 0; k0 < IN_SIZE; k0 += 16) {
#pragma unroll
        for (int i = 0; i < 2; i++) {
            int f4 = tid + i * 256;
            int row = f4 >> 2;
            int kc = (f4 & 3) * 4;
            int gm = m0 + row;
            float4 v = make_float4(0.f, 0.f, 0.f, 0.f);
            if (gm < N_NODES) v = *(const float4*)&x[(size_t)gm * IN_SIZE + k0 + kc];
            float4 h;
            h.x = tf32_rna(v.x);
            h.y = tf32_rna(v.y);
            h.z = tf32_rna(v.z);
            h.w = tf32_rna(v.w);
            *(float4*)&As_hi[row * AS_STRIDE + kc] = h;
        }
#pragma unroll
        for (int i = 0; i < 2; i++) {
            int f4 = tid + i * 256;
            int kr = f4 >> 5;
            int nc = (f4 & 31) * 4;
            float4 v = *(const float4*)&Wt[(size_t)(k0 + kr) * OUT_SIZE + nc];
            float h, l;
            h = tf32_rna(v.x); l = tf32_rna(v.x - h);
            Ws_hi[(nc + 0) * AS_STRIDE + kr] = h; Ws_lo[(nc + 0) * AS_STRIDE + kr] = l;
            h = tf32_rna(v.y); l = tf32_rna(v.y - h);
            Ws_hi[(nc + 1) * AS_STRIDE + kr] = h; Ws_lo[(nc + 1) * AS_STRIDE + kr] = l;
            h = tf32_rna(v.z); l = tf32_rna(v.z - h);
            Ws_hi[(nc + 2) * AS_STRIDE + kr] = h; Ws_lo[(nc + 2) * AS_STRIDE + kr] = l;
            h = tf32_rna(v.w); l = tf32_rna(v.w - h);
            Ws_hi[(nc + 3) * AS_STRIDE + kr] = h; Ws_lo[(nc + 3) * AS_STRIDE + kr] = l;
        }
        __syncthreads();

#pragma unroll
        for (int ks = 0; ks < 16; ks += 8) {
            uint32_t ahi[2][4];
#pragma unroll
            for (int mf = 0; mf < 2; mf++) {
                int r = m_off + mf * 16 + gq;
                int c = ks + tg;
                ahi[mf][0] = __float_as_uint(As_hi[r * AS_STRIDE + c]);
                ahi[mf][1] = __float_as_uint(As_hi[(r + 8) * AS_STRIDE + c]);
                ahi[mf][2] = __float_as_uint(As_hi[r * AS_STRIDE + c + 4]);
                ahi[mf][3] = __float_as_uint(As_hi[(r + 8) * AS_STRIDE + c + 4]);
            }
#pragma unroll
            for (int nf = 0; nf < 8; nf++) {
                uint32_t bhi[2], blo[2];
                int n = n_off + nf * 8 + gq;
                int c = ks + tg;
                bhi[0] = __float_as_uint(Ws_hi[n * AS_STRIDE + c]);
                bhi[1] = __float_as_uint(Ws_hi[n * AS_STRIDE + c + 4]);
                blo[0] = __float_as_uint(Ws_lo[n * AS_STRIDE + c]);
                blo[1] = __float_as_uint(Ws_lo[n * AS_STRIDE + c + 4]);
#pragma unroll
                for (int mf = 0; mf < 2; mf++) {
                    MMA_TF32(acc[mf][nf], ahi[mf], bhi);
                    MMA_TF32(acc[mf][nf], ahi[mf], blo);
                }
            }
        }
        __syncthreads();
    }

    __half* dst = g_Wh + (size_t)et * N_NODES * OUT_SIZE;
#pragma unroll
    for (int mf = 0; mf < 2; mf++) {
#pragma unroll
        for (int nf = 0; nf < 8; nf++) {
            int row = m0 + m_off + mf * 16 + gq;
            int col = n_off + nf * 8 + tg * 2;
            if (row < N_NODES) {
                *(__half2*)&dst[(size_t)row * OUT_SIZE + col] =
                    __floats2half2_rn(acc[mf][nf][0], acc[mf][nf][1]);
            }
            if (row + 8 < N_NODES) {
                *(__half2*)&dst[(size_t)(row + 8) * OUT_SIZE + col] =
                    __floats2half2_rn(acc[mf][nf][2], acc[mf][nf][3]);
            }
        }
    }
}

// ---------------------------------------------------------------------------
// Per-etype gather + mean + bias.
// ---------------------------------------------------------------------------
__global__ __launch_bounds__(256) void gather_kernel(float* __restrict__ out,
                                                     const float* __restrict__ b,
                                                     int et) {
    const int wid = threadIdx.x >> 5;
    const int lane = threadIdx.x & 31;
    const int n = blockIdx.x * 8 + wid;
    if (n >= N_NODES) return;

    const int base = et * N_NODES + n;
    const int beg = __ldg(&g_off[base]);
    const int end = __ldg(&g_off[base + 1]);

    const __half* wh = g_Wh + (size_t)et * N_NODES * OUT_SIZE;
    float4 a0 = make_float4(0.f, 0.f, 0.f, 0.f);
    float4 a1 = make_float4(0.f, 0.f, 0.f, 0.f);

    int j = beg;
    for (; j + 8 <= end; j += 8) {
        int s0 = __ldg(&g_eidx[j + 0]);
        int s1 = __ldg(&g_eidx[j + 1]);
        int s2 = __ldg(&g_eidx[j + 2]);
        int s3 = __ldg(&g_eidx[j + 3]);
        int s4 = __ldg(&g_eidx[j + 4]);
        int s5 = __ldg(&g_eidx[j + 5]);
        int s6 = __ldg(&g_eidx[j + 6]);
        int s7 = __ldg(&g_eidx[j + 7]);
        uint2 u0 = __ldg((const uint2*)&wh[(size_t)s0 * OUT_SIZE + lane * 4]);
        uint2 u1 = __ldg((const uint2*)&wh[(size_t)s1 * OUT_SIZE + lane * 4]);
        uint2 u2 = __ldg((const uint2*)&wh[(size_t)s2 * OUT_SIZE + lane * 4]);
        uint2 u3 = __ldg((const uint2*)&wh[(size_t)s3 * OUT_SIZE + lane * 4]);
        uint2 u4 = __ldg((const uint2*)&wh[(size_t)s4 * OUT_SIZE + lane * 4]);
        uint2 u5 = __ldg((const uint2*)&wh[(size_t)s5 * OUT_SIZE + lane * 4]);
        uint2 u6 = __ldg((const uint2*)&wh[(size_t)s6 * OUT_SIZE + lane * 4]);
        uint2 u7 = __ldg((const uint2*)&wh[(size_t)s7 * OUT_SIZE + lane * 4]);
#define ACC(A, U)                                                            \
        {                                                                    \
            float2 f0 = __half22float2(*(const __half2*)&U.x);               \
            float2 f1 = __half22float2(*(const __half2*)&U.y);               \
            A.x += f0.x; A.y += f0.y; A.z += f1.x; A.w += f1.y;              \
        }
        ACC(a0, u0) ACC(a0, u1) ACC(a0, u2) ACC(a0, u3)
        ACC(a1, u4) ACC(a1, u5) ACC(a1, u6) ACC(a1, u7)
    }
    for (; j < end; j++) {
        int s = __ldg(&g_eidx[j]);
        uint2 u = __ldg((const uint2*)&wh[(size_t)s * OUT_SIZE + lane * 4]);
        ACC(a0, u)
    }
#undef ACC
    a0.x += a1.x; a0.y += a1.y; a0.z += a1.z; a0.w += a1.w;

    float4 r;
    int cnt = end - beg;
    if (cnt > 0) {
        float inv = 1.0f / (float)cnt;
        float4 bb = __ldg(&((const float4*)b)[et * 32 + lane]);
        r.x = a0.x * inv + bb.x;
        r.y = a0.y * inv + bb.y;
        r.z = a0.z * inv + bb.z;
        r.w = a0.w * inv + bb.w;
    } else {
        r = make_float4(0.f, 0.f, 0.f, 0.f);
    }
    ((float4*)out)[((size_t)n * N_ET + et) * 32 + lane] = r;
}

// ---------------------------------------------------------------------------
// Pipelined per-etype fork/join:
//   stream 0 : gemm(0) -> gemm(1) -> gemm(2)       (tensor pipe)
//   s_csr    : CSR build; then gather(et) as soon as gemm(et) lands (L2 pipe)
// gather(0) overlaps gemm(1..2).
// ---------------------------------------------------------------------------
extern "C" void kernel_launch(void* const* d_in, const int* in_sizes, int n_in,
                              void* d_out, int out_size) {
    const float* x    = (const float*)d_in[0];
    const int*   esrc = (const int*)d_in[1];
    const int*   edst = (const int*)d_in[2];
    const float* W    = (const float*)d_in[3];
    const float* b    = (const float*)d_in[4];
    float* out = (float*)d_out;

    static cudaStream_t s_csr = nullptr;
    static cudaEvent_t ev_fork = nullptr, ev_done = nullptr;
    static cudaEvent_t ev_g[N_ET] = {nullptr, nullptr, nullptr};
    if (s_csr == nullptr) {
        cudaStreamCreateWithFlags(&s_csr, cudaStreamNonBlocking);
        cudaEventCreateWithFlags(&ev_fork, cudaEventDisableTiming);
        cudaEventCreateWithFlags(&ev_done, cudaEventDisableTiming);
        for (int e = 0; e < N_ET; e++)
            cudaEventCreateWithFlags(&ev_g[e], cudaEventDisableTiming);
    }

    // Fork
    cudaEventRecord(ev_fork, 0);
    cudaStreamWaitEvent(s_csr, ev_fork, 0);

    // CSR build on s_csr
    hist_kernel<<<(TOTAL_E / 4 + 255) / 256, 256, 0, s_csr>>>(edst);
    scan_a_kernel<<<SCAN_BLOCKS, 256, 0, s_csr>>>();
    scan_b_kernel<<<1, 128, 0, s_csr>>>();
    scan_c_kernel<<<(N_TOT + 255) / 256, 256, 0, s_csr>>>();
    fill_kernel<<<(TOTAL_E / 4 + 255) / 256, 256, 0, s_csr>>>(esrc, edst);

    // GEMMs on stream 0, one per etype, each followed by an event
    for (int e = 0; e < N_ET; e++) {
        gemm_kernel<<<GEMM_BX, 256>>>(x, W, e);
        cudaEventRecord(ev_g[e], 0);
    }

    // Gathers on s_csr: after CSR build (program order) + matching GEMM (event)
    for (int e = 0; e < N_ET; e++) {
        cudaStreamWaitEvent(s_csr, ev_g[e], 0);
        gather_kernel<<<(N_NODES + 7) / 8, 256, 0, s_csr>>>(out, b, e);
    }
    cudaEventRecord(ev_done, s_csr);

    // Join back to the capture stream
    cudaStreamWaitEvent(0, ev_done, 0);
}

// round 9
// speedup vs baseline: 1.3544x; 1.0321x over previous
#include <cuda_runtime.h>
#include <cuda_bf16.h>
#include <cuda_fp16.h>
#include <stdint.h>

#define N_NODES 50000
#define N_EDGES 1000000
#define IN_SIZE 256
#define OUT_SIZE 128
#define N_ET 3
#define N_TOT (N_ET * N_NODES)          // 150000
#define TOTAL_E (N_ET * N_EDGES)        // 3000000
#define SCAN_CHUNK 2048
#define SCAN_BLOCKS ((N_TOT + SCAN_CHUNK - 1) / SCAN_CHUNK)   // 74
#define GEMM_BX ((N_NODES + 127) / 128) // 391

// Scratch: Wh in fp16 (halves gather traffic; 38.4MB, L2-resident)
__device__ __half g_Wh[(size_t)N_ET * N_NODES * OUT_SIZE];
__device__ int   g_cnt[N_TOT];          // zeroed by scan_a after use -> stays zero
__device__ int   g_off[N_TOT + 1];
__device__ int   g_pos[N_TOT];
__device__ int   g_part[SCAN_BLOCKS];
__device__ int   g_eidx[TOTAL_E];       // src node per edge, dst-sorted

// ---------------------------------------------------------------------------
// CSR build
// ---------------------------------------------------------------------------
__global__ void hist_kernel(const int* __restrict__ edst) {
    int base = (blockIdx.x * blockDim.x + threadIdx.x) * 4;
    if (base >= TOTAL_E) return;
    if (base + 4 <= TOTAL_E) {
        int4 d4 = *(const int4*)&edst[base];
        int et0 = base / N_EDGES;
        int et3 = (base + 3) / N_EDGES;
        if (et0 == et3) {
            int o = et0 * N_NODES;
            atomicAdd(&g_cnt[o + d4.x], 1);
            atomicAdd(&g_cnt[o + d4.y], 1);
            atomicAdd(&g_cnt[o + d4.z], 1);
            atomicAdd(&g_cnt[o + d4.w], 1);
        } else {
            atomicAdd(&g_cnt[((base + 0) / N_EDGES) * N_NODES + d4.x], 1);
            atomicAdd(&g_cnt[((base + 1) / N_EDGES) * N_NODES + d4.y], 1);
            atomicAdd(&g_cnt[((base + 2) / N_EDGES) * N_NODES + d4.z], 1);
            atomicAdd(&g_cnt[((base + 3) / N_EDGES) * N_NODES + d4.w], 1);
        }
    } else {
        for (int i = base; i < TOTAL_E; i++)
            atomicAdd(&g_cnt[(i / N_EDGES) * N_NODES + __ldg(&edst[i])], 1);
    }
}

__global__ __launch_bounds__(256) void scan_a_kernel() {
    __shared__ int s[256];
    const int tid = threadIdx.x;
    const int base = blockIdx.x * SCAN_CHUNK + tid * 8;
    int v[8];
    int tsum = 0;
#pragma unroll
    for (int k = 0; k < 8; k++) {
        int i = base + k;
        v[k] = (i < N_TOT) ? g_cnt[i] : 0;
        if (i < N_TOT) g_cnt[i] = 0;        // leave zeroed for next replay
        tsum += v[k];
    }
    s[tid] = tsum;
    __syncthreads();
    for (int off = 1; off < 256; off <<= 1) {
        int t = (tid >= off) ? s[tid - off] : 0;
        __syncthreads();
        s[tid] += t;
        __syncthreads();
    }
    int run = s[tid] - tsum;
#pragma unroll
    for (int k = 0; k < 8; k++) {
        int i = base + k;
        if (i < N_TOT) g_off[i] = run;
        run += v[k];
    }
    if (tid == 255) g_part[blockIdx.x] = s[255];
}

__global__ __launch_bounds__(128) void scan_b_kernel() {
    __shared__ int s[128];
    int tid = threadIdx.x;
    int v = (tid < SCAN_BLOCKS) ? g_part[tid] : 0;
    s[tid] = v;
    __syncthreads();
    for (int off = 1; off < 128; off <<= 1) {
        int t = (tid >= off) ? s[tid - off] : 0;
        __syncthreads();
        s[tid] += t;
        __syncthreads();
    }
    if (tid < SCAN_BLOCKS) g_part[tid] = s[tid] - v;   // exclusive
    if (tid == 127) g_off[N_TOT] = s[127];
}

__global__ void scan_c_kernel() {
    int i = blockIdx.x * blockDim.x + threadIdx.x;
    if (i >= N_TOT) return;
    int o = g_off[i] + g_part[i / SCAN_CHUNK];
    g_off[i] = o;
    g_pos[i] = o;
}

__global__ void fill_kernel(const int* __restrict__ esrc,
                            const int* __restrict__ edst) {
    int base = (blockIdx.x * blockDim.x + threadIdx.x) * 4;
#pragma unroll
    for (int k = 0; k < 4; k++) {
        int i = base + k;
        if (i < TOTAL_E) {
            int et = i / N_EDGES;
            int d = __ldg(&edst[i]);
            int s = __ldg(&esrc[i]);
            int p = atomicAdd(&g_pos[et * N_NODES + d], 1);
            g_eidx[p] = s;
        }
    }
}

// ---------------------------------------------------------------------------
// TF32 helpers
// ---------------------------------------------------------------------------
__device__ __forceinline__ float tf32_rna(float x) {
    uint32_t u;
    asm("cvt.rna.tf32.f32 %0, %1;" : "=r"(u) : "f"(x));
    return __uint_as_float(u);
}

#define MMA_TF32(D, A, B)                                                     \
    asm volatile(                                                             \
        "mma.sync.aligned.m16n8k8.row.col.f32.tf32.tf32.f32 "                 \
        "{%0,%1,%2,%3}, {%4,%5,%6,%7}, {%8,%9}, {%0,%1,%2,%3};"               \
        : "+f"(D[0]), "+f"(D[1]), "+f"(D[2]), "+f"(D[3])                      \
        : "r"(A[0]), "r"(A[1]), "r"(A[2]), "r"(A[3]), "r"(B[0]), "r"(B[1]))

#define AS_STRIDE 20

// ---------------------------------------------------------------------------
// Per-etype GEMM: Wh[et] = x @ W[et], 2-pass TF32 (ahi*bhi + ahi*blo).
// ---------------------------------------------------------------------------
__global__ __launch_bounds__(256, 2) void gemm_kernel(const float* __restrict__ x,
                                                      const float* __restrict__ W,
                                                      int et) {
    const int m0 = blockIdx.x * 128;
    const int tid = threadIdx.x;
    const int wid = tid >> 5;
    const int lane = tid & 31;
    const int m_off = (wid >> 1) * 32;
    const int n_off = (wid & 1) * 64;
    const int gq = lane >> 2;
    const int tg = lane & 3;

    __shared__ float As_hi[128 * AS_STRIDE];
    __shared__ float Ws_hi[128 * AS_STRIDE];   // [n][k]
    __shared__ float Ws_lo[128 * AS_STRIDE];

    const float* Wt = W + (size_t)et * IN_SIZE * OUT_SIZE;

    float acc[2][8][4];
#pragma unroll
    for (int i = 0; i < 2; i++)
#pragma unroll
        for (int j = 0; j < 8; j++)
#pragma unroll
            for (int c = 0; c < 4; c++) acc[i][j][c] = 0.0f;

    for (int k0 = 0; k0 < IN_SIZE; k0 += 16) {
#pragma unroll
        for (int i = 0; i < 2; i++) {
            int f4 = tid + i * 256;
            int row = f4 >> 2;
            int kc = (f4 & 3) * 4;
            int gm = m0 + row;
            float4 v = make_float4(0.f, 0.f, 0.f, 0.f);
            if (gm < N_NODES) v = *(const float4*)&x[(size_t)gm * IN_SIZE + k0 + kc];
            float4 h;
            h.x = tf32_rna(v.x);
            h.y = tf32_rna(v.y);
            h.z = tf32_rna(v.z);
            h.w = tf32_rna(v.w);
            *(float4*)&As_hi[row * AS_STRIDE + kc] = h;
        }
#pragma unroll
        for (int i = 0; i < 2; i++) {
            int f4 = tid + i * 256;
            int kr = f4 >> 5;
            int nc = (f4 & 31) * 4;
            float4 v = *(const float4*)&Wt[(size_t)(k0 + kr) * OUT_SIZE + nc];
            float h, l;
            h = tf32_rna(v.x); l = tf32_rna(v.x - h);
            Ws_hi[(nc + 0) * AS_STRIDE + kr] = h; Ws_lo[(nc + 0) * AS_STRIDE + kr] = l;
            h = tf32_rna(v.y); l = tf32_rna(v.y - h);
            Ws_hi[(nc + 1) * AS_STRIDE + kr] = h; Ws_lo[(nc + 1) * AS_STRIDE + kr] = l;
            h = tf32_rna(v.z); l = tf32_rna(v.z - h);
            Ws_hi[(nc + 2) * AS_STRIDE + kr] = h; Ws_lo[(nc + 2) * AS_STRIDE + kr] = l;
            h = tf32_rna(v.w); l = tf32_rna(v.w - h);
            Ws_hi[(nc + 3) * AS_STRIDE + kr] = h; Ws_lo[(nc + 3) * AS_STRIDE + kr] = l;
        }
        __syncthreads();

#pragma unroll
        for (int ks = 0; ks < 16; ks += 8) {
            uint32_t ahi[2][4];
#pragma unroll
            for (int mf = 0; mf < 2; mf++) {
                int r = m_off + mf * 16 + gq;
                int c = ks + tg;
                ahi[mf][0] = __float_as_uint(As_hi[r * AS_STRIDE + c]);
                ahi[mf][1] = __float_as_uint(As_hi[(r + 8) * AS_STRIDE + c]);
                ahi[mf][2] = __float_as_uint(As_hi[r * AS_STRIDE + c + 4]);
                ahi[mf][3] = __float_as_uint(As_hi[(r + 8) * AS_STRIDE + c + 4]);
            }
#pragma unroll
            for (int nf = 0; nf < 8; nf++) {
                uint32_t bhi[2], blo[2];
                int n = n_off + nf * 8 + gq;
                int c = ks + tg;
                bhi[0] = __float_as_uint(Ws_hi[n * AS_STRIDE + c]);
                bhi[1] = __float_as_uint(Ws_hi[n * AS_STRIDE + c + 4]);
                blo[0] = __float_as_uint(Ws_lo[n * AS_STRIDE + c]);
                blo[1] = __float_as_uint(Ws_lo[n * AS_STRIDE + c + 4]);
#pragma unroll
                for (int mf = 0; mf < 2; mf++) {
                    MMA_TF32(acc[mf][nf], ahi[mf], bhi);
                    MMA_TF32(acc[mf][nf], ahi[mf], blo);
                }
            }
        }
        __syncthreads();
    }

    __half* dst = g_Wh + (size_t)et * N_NODES * OUT_SIZE;
#pragma unroll
    for (int mf = 0; mf < 2; mf++) {
#pragma unroll
        for (int nf = 0; nf < 8; nf++) {
            int row = m0 + m_off + mf * 16 + gq;
            int col = n_off + nf * 8 + tg * 2;
            if (row < N_NODES) {
                *(__half2*)&dst[(size_t)row * OUT_SIZE + col] =
                    __floats2half2_rn(acc[mf][nf][0], acc[mf][nf][1]);
            }
            if (row + 8 < N_NODES) {
                *(__half2*)&dst[(size_t)(row + 8) * OUT_SIZE + col] =
                    __floats2half2_rn(acc[mf][nf][2], acc[mf][nf][3]);
            }
        }
    }
}

// ---------------------------------------------------------------------------
// Per-etype gather + mean + bias.
// ---------------------------------------------------------------------------
__global__ __launch_bounds__(256) void gather_kernel(float* __restrict__ out,
                                                     const float* __restrict__ b,
                                                     int et) {
    const int wid = threadIdx.x >> 5;
    const int lane = threadIdx.x & 31;
    const int n = blockIdx.x * 8 + wid;
    if (n >= N_NODES) return;

    const int base = et * N_NODES + n;
    const int beg = __ldg(&g_off[base]);
    const int end = __ldg(&g_off[base + 1]);

    const __half* wh = g_Wh + (size_t)et * N_NODES * OUT_SIZE;
    float4 a0 = make_float4(0.f, 0.f, 0.f, 0.f);
    float4 a1 = make_float4(0.f, 0.f, 0.f, 0.f);

    int j = beg;
    for (; j + 8 <= end; j += 8) {
        int s0 = __ldg(&g_eidx[j + 0]);
        int s1 = __ldg(&g_eidx[j + 1]);
        int s2 = __ldg(&g_eidx[j + 2]);
        int s3 = __ldg(&g_eidx[j + 3]);
        int s4 = __ldg(&g_eidx[j + 4]);
        int s5 = __ldg(&g_eidx[j + 5]);
        int s6 = __ldg(&g_eidx[j + 6]);
        int s7 = __ldg(&g_eidx[j + 7]);
        uint2 u0 = __ldg((const uint2*)&wh[(size_t)s0 * OUT_SIZE + lane * 4]);
        uint2 u1 = __ldg((const uint2*)&wh[(size_t)s1 * OUT_SIZE + lane * 4]);
        uint2 u2 = __ldg((const uint2*)&wh[(size_t)s2 * OUT_SIZE + lane * 4]);
        uint2 u3 = __ldg((const uint2*)&wh[(size_t)s3 * OUT_SIZE + lane * 4]);
        uint2 u4 = __ldg((const uint2*)&wh[(size_t)s4 * OUT_SIZE + lane * 4]);
        uint2 u5 = __ldg((const uint2*)&wh[(size_t)s5 * OUT_SIZE + lane * 4]);
        uint2 u6 = __ldg((const uint2*)&wh[(size_t)s6 * OUT_SIZE + lane * 4]);
        uint2 u7 = __ldg((const uint2*)&wh[(size_t)s7 * OUT_SIZE + lane * 4]);
#define ACC(A, U)                                                            \
        {                                                                    \
            float2 f0 = __half22float2(*(const __half2*)&U.x);               \
            float2 f1 = __half22float2(*(const __half2*)&U.y);               \
            A.x += f0.x; A.y += f0.y; A.z += f1.x; A.w += f1.y;              \
        }
        ACC(a0, u0) ACC(a0, u1) ACC(a0, u2) ACC(a0, u3)
        ACC(a1, u4) ACC(a1, u5) ACC(a1, u6) ACC(a1, u7)
    }
    for (; j < end; j++) {
        int s = __ldg(&g_eidx[j]);
        uint2 u = __ldg((const uint2*)&wh[(size_t)s * OUT_SIZE + lane * 4]);
        ACC(a0, u)
    }
#undef ACC
    a0.x += a1.x; a0.y += a1.y; a0.z += a1.z; a0.w += a1.w;

    float4 r;
    int cnt = end - beg;
    if (cnt > 0) {
        float inv = 1.0f / (float)cnt;
        float4 bb = __ldg(&((const float4*)b)[et * 32 + lane]);
        r.x = a0.x * inv + bb.x;
        r.y = a0.y * inv + bb.y;
        r.z = a0.z * inv + bb.z;
        r.w = a0.w * inv + bb.w;
    } else {
        r = make_float4(0.f, 0.f, 0.f, 0.f);
    }
    ((float4*)out)[((size_t)n * N_ET + et) * 32 + lane] = r;
}

// ---------------------------------------------------------------------------
// Two-stream pipelined schedule (kept at round-7 graph complexity to stay
// under the graph-upload memory threshold):
//   stream 0 : gemm0 -> gemm1 -> gemm2 -> (wait fill) gather2
//   s_csr    : CSR chain -> (wait gemm0) gather0 -> (wait gemm1) gather1
// gather0/1 overlap gemm1/2 and gather2.
// ---------------------------------------------------------------------------
extern "C" void kernel_launch(void* const* d_in, const int* in_sizes, int n_in,
                              void* d_out, int out_size) {
    const float* x    = (const float*)d_in[0];
    const int*   esrc = (const int*)d_in[1];
    const int*   edst = (const int*)d_in[2];
    const float* W    = (const float*)d_in[3];
    const float* b    = (const float*)d_in[4];
    float* out = (float*)d_out;

    static cudaStream_t s_csr = nullptr;
    static cudaEvent_t ev_fork = nullptr, ev_fill = nullptr, ev_done = nullptr;
    static cudaEvent_t ev_g0 = nullptr, ev_g1 = nullptr;
    if (s_csr == nullptr) {
        cudaStreamCreateWithFlags(&s_csr, cudaStreamNonBlocking);
        cudaEventCreateWithFlags(&ev_fork, cudaEventDisableTiming);
        cudaEventCreateWithFlags(&ev_fill, cudaEventDisableTiming);
        cudaEventCreateWithFlags(&ev_done, cudaEventDisableTiming);
        cudaEventCreateWithFlags(&ev_g0, cudaEventDisableTiming);
        cudaEventCreateWithFlags(&ev_g1, cudaEventDisableTiming);
    }

    // Fork
    cudaEventRecord(ev_fork, 0);
    cudaStreamWaitEvent(s_csr, ev_fork, 0);

    // CSR build on s_csr
    hist_kernel<<<(TOTAL_E / 4 + 255) / 256, 256, 0, s_csr>>>(edst);
    scan_a_kernel<<<SCAN_BLOCKS, 256, 0, s_csr>>>();
    scan_b_kernel<<<1, 128, 0, s_csr>>>();
    scan_c_kernel<<<(N_TOT + 255) / 256, 256, 0, s_csr>>>();
    fill_kernel<<<(TOTAL_E / 4 + 255) / 256, 256, 0, s_csr>>>(esrc, edst);
    cudaEventRecord(ev_fill, s_csr);

    // GEMMs on stream 0, events after the first two
    gemm_kernel<<<GEMM_BX, 256>>>(x, W, 0);
    cudaEventRecord(ev_g0, 0);
    gemm_kernel<<<GEMM_BX, 256>>>(x, W, 1);
    cudaEventRecord(ev_g1, 0);
    gemm_kernel<<<GEMM_BX, 256>>>(x, W, 2);

    // s_csr consumes etypes 0 and 1
    cudaStreamWaitEvent(s_csr, ev_g0, 0);
    gather_kernel<<<(N_NODES + 7) / 8, 256, 0, s_csr>>>(out, b, 0);
    cudaStreamWaitEvent(s_csr, ev_g1, 0);
    gather_kernel<<<(N_NODES + 7) / 8, 256, 0, s_csr>>>(out, b, 1);
    cudaEventRecord(ev_done, s_csr);

    // stream 0 consumes etype 2 (after its own gemm2 + fill)
    cudaStreamWaitEvent(0, ev_fill, 0);
    gather_kernel<<<(N_NODES + 7) / 8, 256>>>(out, b, 2);

    // Join
    cudaStreamWaitEvent(0, ev_done, 0);
}

// round 10
// speedup vs baseline: 2.0618x; 1.5223x over previous
#include <cuda_runtime.h>
#include <cuda_bf16.h>
#include <cuda_fp16.h>
#include <stdint.h>

#define N_NODES 50000
#define N_EDGES 1000000
#define IN_SIZE 256
#define OUT_SIZE 128
#define N_ET 3
#define N_TOT (N_ET * N_NODES)          // 150000
#define TOTAL_E (N_ET * N_EDGES)        // 3000000
#define SCAN_CHUNK 2048
#define SCAN_BLOCKS ((N_TOT + SCAN_CHUNK - 1) / SCAN_CHUNK)   // 74
#define GEMM_BX ((N_NODES + 127) / 128) // 391

// Scratch: Wh in fp16 (halves gather traffic; 38.4MB, L2-resident)
__device__ __half g_Wh[(size_t)N_ET * N_NODES * OUT_SIZE];
__device__ int   g_cnt[N_TOT];          // zeroed by scan_a after use -> stays zero
__device__ int   g_off[N_TOT + 1];
__device__ int   g_pos[N_TOT];
__device__ int   g_part[SCAN_BLOCKS];
__device__ int   g_eidx[TOTAL_E];       // src node per edge, dst-sorted

// ---------------------------------------------------------------------------
// CSR build
// ---------------------------------------------------------------------------
__global__ void hist_kernel(const int* __restrict__ edst) {
    int base = (blockIdx.x * blockDim.x + threadIdx.x) * 4;
    if (base >= TOTAL_E) return;
    if (base + 4 <= TOTAL_E) {
        int4 d4 = *(const int4*)&edst[base];
        int et0 = base / N_EDGES;
        int et3 = (base + 3) / N_EDGES;
        if (et0 == et3) {
            int o = et0 * N_NODES;
            atomicAdd(&g_cnt[o + d4.x], 1);
            atomicAdd(&g_cnt[o + d4.y], 1);
            atomicAdd(&g_cnt[o + d4.z], 1);
            atomicAdd(&g_cnt[o + d4.w], 1);
        } else {
            atomicAdd(&g_cnt[((base + 0) / N_EDGES) * N_NODES + d4.x], 1);
            atomicAdd(&g_cnt[((base + 1) / N_EDGES) * N_NODES + d4.y], 1);
            atomicAdd(&g_cnt[((base + 2) / N_EDGES) * N_NODES + d4.z], 1);
            atomicAdd(&g_cnt[((base + 3) / N_EDGES) * N_NODES + d4.w], 1);
        }
    } else {
        for (int i = base; i < TOTAL_E; i++)
            atomicAdd(&g_cnt[(i / N_EDGES) * N_NODES + __ldg(&edst[i])], 1);
    }
}

__global__ __launch_bounds__(256) void scan_a_kernel() {
    __shared__ int s[256];
    const int tid = threadIdx.x;
    const int base = blockIdx.x * SCAN_CHUNK + tid * 8;
    int v[8];
    int tsum = 0;
#pragma unroll
    for (int k = 0; k < 8; k++) {
        int i = base + k;
        v[k] = (i < N_TOT) ? g_cnt[i] : 0;
        if (i < N_TOT) g_cnt[i] = 0;        // leave zeroed for next replay
        tsum += v[k];
    }
    s[tid] = tsum;
    __syncthreads();
    for (int off = 1; off < 256; off <<= 1) {
        int t = (tid >= off) ? s[tid - off] : 0;
        __syncthreads();
        s[tid] += t;
        __syncthreads();
    }
    int run = s[tid] - tsum;
#pragma unroll
    for (int k = 0; k < 8; k++) {
        int i = base + k;
        if (i < N_TOT) g_off[i] = run;
        run += v[k];
    }
    if (tid == 255) g_part[blockIdx.x] = s[255];
}

__global__ __launch_bounds__(128) void scan_b_kernel() {
    __shared__ int s[128];
    int tid = threadIdx.x;
    int v = (tid < SCAN_BLOCKS) ? g_part[tid] : 0;
    s[tid] = v;
    __syncthreads();
    for (int off = 1; off < 128; off <<= 1) {
        int t = (tid >= off) ? s[tid - off] : 0;
        __syncthreads();
        s[tid] += t;
        __syncthreads();
    }
    if (tid < SCAN_BLOCKS) g_part[tid] = s[tid] - v;   // exclusive
    if (tid == 127) g_off[N_TOT] = s[127];
}

__global__ void scan_c_kernel() {
    int i = blockIdx.x * blockDim.x + threadIdx.x;
    if (i >= N_TOT) return;
    int o = g_off[i] + g_part[i / SCAN_CHUNK];
    g_off[i] = o;
    g_pos[i] = o;
}

__global__ void fill_kernel(const int* __restrict__ esrc,
                            const int* __restrict__ edst) {
    int base = (blockIdx.x * blockDim.x + threadIdx.x) * 4;
#pragma unroll
    for (int k = 0; k < 4; k++) {
        int i = base + k;
        if (i < TOTAL_E) {
            int et = i / N_EDGES;
            int d = __ldg(&edst[i]);
            int s = __ldg(&esrc[i]);
            int p = atomicAdd(&g_pos[et * N_NODES + d], 1);
            g_eidx[p] = s;
        }
    }
}

// ---------------------------------------------------------------------------
// bf16-split GEMM helpers
// ---------------------------------------------------------------------------
#define MMA_BF16(D, A, B)                                                     \
    asm volatile(                                                             \
        "mma.sync.aligned.m16n8k16.row.col.f32.bf16.bf16.f32 "                \
        "{%0,%1,%2,%3}, {%4,%5,%6,%7}, {%8,%9}, {%0,%1,%2,%3};"               \
        : "+f"(D[0]), "+f"(D[1]), "+f"(D[2]), "+f"(D[3])                      \
        : "r"(A[0]), "r"(A[1]), "r"(A[2]), "r"(A[3]), "r"(B[0]), "r"(B[1]))

__device__ __forceinline__ void bf16_split2(float a, float b,
                                            uint32_t& hi, uint32_t& lo) {
    __nv_bfloat162 h, l;
    h.x = __float2bfloat16(a);
    h.y = __float2bfloat16(b);
    l.x = __float2bfloat16(a - __bfloat162float(h.x));
    l.y = __float2bfloat16(b - __bfloat162float(h.y));
    hi = *(uint32_t*)&h;
    lo = *(uint32_t*)&l;
}

#define PS 12   // pair-stride: 8 k-pairs + 4 pad (12*gq+tg covers all banks)

// ---------------------------------------------------------------------------
// Per-etype GEMM: Wh[et] = x @ W[et], split-bf16 (3x m16n8k16 per k-tile).
// x = ahi+alo, W = bhi+blo (bf16); acc += ahi*bhi + ahi*blo + alo*bhi.
// ---------------------------------------------------------------------------
__global__ __launch_bounds__(256, 2) void gemm_kernel(const float* __restrict__ x,
                                                      const float* __restrict__ W,
                                                      int et) {
    const int m0 = blockIdx.x * 128;
    const int tid = threadIdx.x;
    const int wid = tid >> 5;
    const int lane = tid & 31;
    const int m_off = (wid >> 1) * 32;
    const int n_off = (wid & 1) * 64;
    const int gq = lane >> 2;            // 0..7
    const int tg = lane & 3;             // 0..3

    __shared__ uint32_t Ah[128 * PS];    // x hi pairs: [row][k/2]
    __shared__ uint32_t Al[128 * PS];
    __shared__ uint32_t Bh[128 * PS];    // W hi pairs: [n][k/2]
    __shared__ uint32_t Bl[128 * PS];

    const float* Wt = W + (size_t)et * IN_SIZE * OUT_SIZE;

    float acc[2][8][4];
#pragma unroll
    for (int i = 0; i < 2; i++)
#pragma unroll
        for (int j = 0; j < 8; j++)
#pragma unroll
            for (int c = 0; c < 4; c++) acc[i][j][c] = 0.0f;

    const int wn = tid & 127;            // W-tile: this thread's n
    const int wkh = tid >> 7;            // W-tile: k half (0: k0..7, 1: k8..15)

    for (int k0 = 0; k0 < IN_SIZE; k0 += 16) {
        // -- x tile: 128 rows x 16 k; each thread does 2 float4 -> 2x2 pairs
#pragma unroll
        for (int i = 0; i < 2; i++) {
            int f4 = tid + i * 256;
            int row = f4 >> 2;
            int kc = (f4 & 3) * 4;       // 0,4,8,12
            int gm = m0 + row;
            float4 v = make_float4(0.f, 0.f, 0.f, 0.f);
            if (gm < N_NODES) v = *(const float4*)&x[(size_t)gm * IN_SIZE + k0 + kc];
            uint32_t h0, l0, h1, l1;
            bf16_split2(v.x, v.y, h0, l0);
            bf16_split2(v.z, v.w, h1, l1);
            int p = row * PS + (kc >> 1);
            Ah[p] = h0; Ah[p + 1] = h1;
            Al[p] = l0; Al[p + 1] = l1;
        }
        // -- W tile: 16 k x 128 n, transposed to [n][k-pairs].
        // Thread (wn, wkh) loads 8 consecutive k for its n (coalesced over n).
        {
            float w[8];
#pragma unroll
            for (int i = 0; i < 8; i++)
                w[i] = __ldg(&Wt[(size_t)(k0 + wkh * 8 + i) * OUT_SIZE + wn]);
            int p = wn * PS + wkh * 4;
#pragma unroll
            for (int q = 0; q < 4; q++) {
                uint32_t h, l;
                bf16_split2(w[2 * q], w[2 * q + 1], h, l);
                Bh[p + q] = h;
                Bl[p + q] = l;
            }
        }
        __syncthreads();

        // -- fragments + MMA
        uint32_t ahi[2][4], alo[2][4];
#pragma unroll
        for (int mf = 0; mf < 2; mf++) {
            int r = (m_off + mf * 16 + gq) * PS;
            ahi[mf][0] = Ah[r + tg];
            ahi[mf][1] = Ah[r + 8 * PS + tg];
            ahi[mf][2] = Ah[r + 4 + tg];
            ahi[mf][3] = Ah[r + 8 * PS + 4 + tg];
            alo[mf][0] = Al[r + tg];
            alo[mf][1] = Al[r + 8 * PS + tg];
            alo[mf][2] = Al[r + 4 + tg];
            alo[mf][3] = Al[r + 8 * PS + 4 + tg];
        }
#pragma unroll
        for (int nf = 0; nf < 8; nf++) {
            int n = (n_off + nf * 8 + gq) * PS;
            uint32_t bhi[2], blo[2];
            bhi[0] = Bh[n + tg];
            bhi[1] = Bh[n + 4 + tg];
            blo[0] = Bl[n + tg];
            blo[1] = Bl[n + 4 + tg];
#pragma unroll
            for (int mf = 0; mf < 2; mf++) {
                MMA_BF16(acc[mf][nf], ahi[mf], bhi);
                MMA_BF16(acc[mf][nf], ahi[mf], blo);
                MMA_BF16(acc[mf][nf], alo[mf], bhi);
            }
        }
        __syncthreads();
    }

    __half* dst = g_Wh + (size_t)et * N_NODES * OUT_SIZE;
#pragma unroll
    for (int mf = 0; mf < 2; mf++) {
#pragma unroll
        for (int nf = 0; nf < 8; nf++) {
            int row = m0 + m_off + mf * 16 + gq;
            int col = n_off + nf * 8 + tg * 2;
            if (row < N_NODES) {
                *(__half2*)&dst[(size_t)row * OUT_SIZE + col] =
                    __floats2half2_rn(acc[mf][nf][0], acc[mf][nf][1]);
            }
            if (row + 8 < N_NODES) {
                *(__half2*)&dst[(size_t)(row + 8) * OUT_SIZE + col] =
                    __floats2half2_rn(acc[mf][nf][2], acc[mf][nf][3]);
            }
        }
    }
}

// ---------------------------------------------------------------------------
// Per-etype gather + mean + bias: 16-deep MLP primary stage, then 8, then 1.
// ---------------------------------------------------------------------------
__global__ __launch_bounds__(256) void gather_kernel(float* __restrict__ out,
                                                     const float* __restrict__ b,
                                                     int et) {
    const int wid = threadIdx.x >> 5;
    const int lane = threadIdx.x & 31;
    const int n = blockIdx.x * 8 + wid;
    if (n >= N_NODES) return;

    const int base = et * N_NODES + n;
    const int beg = __ldg(&g_off[base]);
    const int end = __ldg(&g_off[base + 1]);

    const __half* wh = g_Wh + (size_t)et * N_NODES * OUT_SIZE;
    float4 a0 = make_float4(0.f, 0.f, 0.f, 0.f);
    float4 a1 = make_float4(0.f, 0.f, 0.f, 0.f);

#define ACC(A, U)                                                            \
    {                                                                        \
        float2 f0 = __half22float2(*(const __half2*)&U.x);                   \
        float2 f1 = __half22float2(*(const __half2*)&U.y);                   \
        A.x += f0.x; A.y += f0.y; A.z += f1.x; A.w += f1.y;                  \
    }

    int j = beg;
    for (; j + 16 <= end; j += 16) {
        int s[16];
#pragma unroll
        for (int k = 0; k < 16; k++) s[k] = __ldg(&g_eidx[j + k]);
        uint2 u[16];
#pragma unroll
        for (int k = 0; k < 16; k++)
            u[k] = __ldg((const uint2*)&wh[(size_t)s[k] * OUT_SIZE + lane * 4]);
#pragma unroll
        for (int k = 0; k < 8; k++) ACC(a0, u[k])
#pragma unroll
        for (int k = 8; k < 16; k++) ACC(a1, u[k])
    }
    for (; j + 8 <= end; j += 8) {
        int s[8];
#pragma unroll
        for (int k = 0; k < 8; k++) s[k] = __ldg(&g_eidx[j + k]);
        uint2 u[8];
#pragma unroll
        for (int k = 0; k < 8; k++)
            u[k] = __ldg((const uint2*)&wh[(size_t)s[k] * OUT_SIZE + lane * 4]);
#pragma unroll
        for (int k = 0; k < 4; k++) ACC(a0, u[k])
#pragma unroll
        for (int k = 4; k < 8; k++) ACC(a1, u[k])
    }
    for (; j < end; j++) {
        int s = __ldg(&g_eidx[j]);
        uint2 u = __ldg((const uint2*)&wh[(size_t)s * OUT_SIZE + lane * 4]);
        ACC(a0, u)
    }
#undef ACC
    a0.x += a1.x; a0.y += a1.y; a0.z += a1.z; a0.w += a1.w;

    float4 r;
    int cnt = end - beg;
    if (cnt > 0) {
        float inv = 1.0f / (float)cnt;
        float4 bb = __ldg(&((const float4*)b)[et * 32 + lane]);
        r.x = a0.x * inv + bb.x;
        r.y = a0.y * inv + bb.y;
        r.z = a0.z * inv + bb.z;
        r.w = a0.w * inv + bb.w;
    } else {
        r = make_float4(0.f, 0.f, 0.f, 0.f);
    }
    ((float4*)out)[((size_t)n * N_ET + et) * 32 + lane] = r;
}

// ---------------------------------------------------------------------------
// Two-stream pipelined schedule (round-9 topology, passes teardown check):
//   stream 0 : gemm0 -> gemm1 -> gemm2 -> (wait fill) gather2
//   s_csr    : CSR chain -> (wait gemm0) gather0 -> (wait gemm1) gather1
// ---------------------------------------------------------------------------
extern "C" void kernel_launch(void* const* d_in, const int* in_sizes, int n_in,
                              void* d_out, int out_size) {
    const float* x    = (const float*)d_in[0];
    const int*   esrc = (const int*)d_in[1];
    const int*   edst = (const int*)d_in[2];
    const float* W    = (const float*)d_in[3];
    const float* b    = (const float*)d_in[4];
    float* out = (float*)d_out;

    static cudaStream_t s_csr = nullptr;
    static cudaEvent_t ev_fork = nullptr, ev_fill = nullptr, ev_done = nullptr;
    static cudaEvent_t ev_g0 = nullptr, ev_g1 = nullptr;
    if (s_csr == nullptr) {
        cudaStreamCreateWithFlags(&s_csr, cudaStreamNonBlocking);
        cudaEventCreateWithFlags(&ev_fork, cudaEventDisableTiming);
        cudaEventCreateWithFlags(&ev_fill, cudaEventDisableTiming);
        cudaEventCreateWithFlags(&ev_done, cudaEventDisableTiming);
        cudaEventCreateWithFlags(&ev_g0, cudaEventDisableTiming);
        cudaEventCreateWithFlags(&ev_g1, cudaEventDisableTiming);
    }

    // Fork
    cudaEventRecord(ev_fork, 0);
    cudaStreamWaitEvent(s_csr, ev_fork, 0);

    // CSR build on s_csr
    hist_kernel<<<(TOTAL_E / 4 + 255) / 256, 256, 0, s_csr>>>(edst);
    scan_a_kernel<<<SCAN_BLOCKS, 256, 0, s_csr>>>();
    scan_b_kernel<<<1, 128, 0, s_csr>>>();
    scan_c_kernel<<<(N_TOT + 255) / 256, 256, 0, s_csr>>>();
    fill_kernel<<<(TOTAL_E / 4 + 255) / 256, 256, 0, s_csr>>>(esrc, edst);
    cudaEventRecord(ev_fill, s_csr);

    // GEMMs on stream 0
    gemm_kernel<<<GEMM_BX, 256>>>(x, W, 0);
    cudaEventRecord(ev_g0, 0);
    gemm_kernel<<<GEMM_BX, 256>>>(x, W, 1);
    cudaEventRecord(ev_g1, 0);
    gemm_kernel<<<GEMM_BX, 256>>>(x, W, 2);

    // s_csr consumes etypes 0 and 1
    cudaStreamWaitEvent(s_csr, ev_g0, 0);
    gather_kernel<<<(N_NODES + 7) / 8, 256, 0, s_csr>>>(out, b, 0);
    cudaStreamWaitEvent(s_csr, ev_g1, 0);
    gather_kernel<<<(N_NODES + 7) / 8, 256, 0, s_csr>>>(out, b, 1);
    cudaEventRecord(ev_done, s_csr);

    // stream 0 consumes etype 2
    cudaStreamWaitEvent(0, ev_fill, 0);
    gather_kernel<<<(N_NODES + 7) / 8, 256>>>(out, b, 2);

    // Join
    cudaStreamWaitEvent(0, ev_done, 0);
}